// round 2
// baseline (speedup 1.0000x reference)
#include <cuda_runtime.h>
#include <math.h>

// Problem constants
#define TOKENS 8192      // B*N = 4*2048
#define NSEQ   2048
#define CDIM   1024
#define MLPH   4096
#define NHEADS 16
#define DHEAD  64
#define LN_EPS 1e-5f

// ---------------------------------------------------------------------------
// Scratch: one big __device__ array (no runtime allocation allowed).
// ---------------------------------------------------------------------------
#define SLAB 8388608ull   // 8192*1024
__device__ float g_scratch[9ull * SLAB + (unsigned long long)TOKENS * MLPH];

// ---------------------------------------------------------------------------
// Block-wide reduction of a float4 (sum of each component), 256 threads.
// ---------------------------------------------------------------------------
__device__ __forceinline__ float4 blockReduce4(float4 v) {
    __shared__ float4 red[8];
    #pragma unroll
    for (int o = 16; o > 0; o >>= 1) {
        v.x += __shfl_xor_sync(0xffffffffu, v.x, o);
        v.y += __shfl_xor_sync(0xffffffffu, v.y, o);
        v.z += __shfl_xor_sync(0xffffffffu, v.z, o);
        v.w += __shfl_xor_sync(0xffffffffu, v.w, o);
    }
    int w = threadIdx.x >> 5;
    if ((threadIdx.x & 31) == 0) red[w] = v;
    __syncthreads();
    v = red[threadIdx.x & 7];
    #pragma unroll
    for (int o = 4; o > 0; o >>= 1) {
        v.x += __shfl_xor_sync(0xffffffffu, v.x, o);
        v.y += __shfl_xor_sync(0xffffffffu, v.y, o);
        v.z += __shfl_xor_sync(0xffffffffu, v.z, o);
        v.w += __shfl_xor_sync(0xffffffffu, v.w, o);
    }
    return v;
}

// ---------------------------------------------------------------------------
// LN for q/k/v inputs. One block (256 thr) per token. k,v share stats of x+pe.
// ---------------------------------------------------------------------------
__global__ __launch_bounds__(256) void ln_qkv_kernel(
    const float* __restrict__ x, const float* __restrict__ pe,
    const float* __restrict__ nqg, const float* __restrict__ nqb,
    const float* __restrict__ nkg, const float* __restrict__ nkb,
    const float* __restrict__ nvg, const float* __restrict__ nvb,
    float* __restrict__ lnq, float* __restrict__ lnk, float* __restrict__ lnv)
{
    int t = blockIdx.x;
    int n = t & (NSEQ - 1);
    int tid = threadIdx.x;

    const float4* xr = (const float4*)(x + (size_t)t * CDIM);
    const float4* pr = (const float4*)(pe + (size_t)n * CDIM);
    float4 xv = xr[tid];
    float4 pv = pr[tid];
    float4 xp = make_float4(xv.x + pv.x, xv.y + pv.y, xv.z + pv.z, xv.w + pv.w);

    float4 s;
    s.x = xv.x + xv.y + xv.z + xv.w;
    s.y = xv.x * xv.x + xv.y * xv.y + xv.z * xv.z + xv.w * xv.w;
    s.z = xp.x + xp.y + xp.z + xp.w;
    s.w = xp.x * xp.x + xp.y * xp.y + xp.z * xp.z + xp.w * xp.w;
    s = blockReduce4(s);

    const float inv = 1.0f / (float)CDIM;
    float m1 = s.x * inv, v1 = s.y * inv - m1 * m1;
    float r1 = rsqrtf(v1 + LN_EPS);
    float m2 = s.z * inv, v2 = s.w * inv - m2 * m2;
    float r2 = rsqrtf(v2 + LN_EPS);

    float4 g, b, o;
    size_t base = (size_t)t * CDIM;

    g = ((const float4*)nqg)[tid]; b = ((const float4*)nqb)[tid];
    o.x = (xv.x - m1) * r1 * g.x + b.x;
    o.y = (xv.y - m1) * r1 * g.y + b.y;
    o.z = (xv.z - m1) * r1 * g.z + b.z;
    o.w = (xv.w - m1) * r1 * g.w + b.w;
    ((float4*)(lnq + base))[tid] = o;

    float4 nrm;
    nrm.x = (xp.x - m2) * r2; nrm.y = (xp.y - m2) * r2;
    nrm.z = (xp.z - m2) * r2; nrm.w = (xp.w - m2) * r2;

    g = ((const float4*)nkg)[tid]; b = ((const float4*)nkb)[tid];
    o.x = nrm.x * g.x + b.x; o.y = nrm.y * g.y + b.y;
    o.z = nrm.z * g.z + b.z; o.w = nrm.w * g.w + b.w;
    ((float4*)(lnk + base))[tid] = o;

    g = ((const float4*)nvg)[tid]; b = ((const float4*)nvb)[tid];
    o.x = nrm.x * g.x + b.x; o.y = nrm.y * g.y + b.y;
    o.z = nrm.z * g.z + b.z; o.w = nrm.w * g.w + b.w;
    ((float4*)(lnv + base))[tid] = o;
}

// ---------------------------------------------------------------------------
// Plain LN (for h -> lnh).
// ---------------------------------------------------------------------------
__global__ __launch_bounds__(256) void ln_kernel(
    const float* __restrict__ in, const float* __restrict__ gg,
    const float* __restrict__ bb, float* __restrict__ out)
{
    int t = blockIdx.x;
    int tid = threadIdx.x;
    const float4* xr = (const float4*)(in + (size_t)t * CDIM);
    float4 xv = xr[tid];
    float4 s;
    s.x = xv.x + xv.y + xv.z + xv.w;
    s.y = xv.x * xv.x + xv.y * xv.y + xv.z * xv.z + xv.w * xv.w;
    s.z = 0.f; s.w = 0.f;
    s = blockReduce4(s);
    const float inv = 1.0f / (float)CDIM;
    float m = s.x * inv, v = s.y * inv - m * m;
    float r = rsqrtf(v + LN_EPS);
    float4 g = ((const float4*)gg)[tid];
    float4 b = ((const float4*)bb)[tid];
    float4 o;
    o.x = (xv.x - m) * r * g.x + b.x;
    o.y = (xv.y - m) * r * g.y + b.y;
    o.z = (xv.z - m) * r * g.z + b.z;
    o.w = (xv.w - m) * r * g.w + b.w;
    ((float4*)(out + (size_t)t * CDIM))[tid] = o;
}

// ---------------------------------------------------------------------------
// Tiled fp32 GEMM: Y[M,N] = X[M,K] @ W[K,N] + bias, 128x128x8, 256 thr, 8x8.
// EPI: 0 = bias ; 1 = bias + LeakyReLU(0.1) ; 2 = bias + residual
// ---------------------------------------------------------------------------
template <int EPI>
__global__ __launch_bounds__(256) void gemm_kernel(
    const float* __restrict__ X, const float* __restrict__ W,
    const float* __restrict__ bias, const float* __restrict__ Res,
    float* __restrict__ Y, int M, int N, int K)
{
    __shared__ float As[8][128];
    __shared__ float Bs[8][128];

    int tid = threadIdx.x;
    int bm = blockIdx.y * 128;
    int bn = blockIdx.x * 128;

    int lr = tid >> 1;           // A tile row   (0..127)
    int lc = (tid & 1) * 4;      // A tile k off (0 or 4)
    int wr = tid >> 5;           // B tile k row (0..7)
    int wc = (tid & 31) * 4;     // B tile col   (0..124)

    int trow = (tid >> 4) * 8;
    int tcol = (tid & 15) * 8;

    float acc[8][8];
    #pragma unroll
    for (int i = 0; i < 8; i++)
        #pragma unroll
        for (int j = 0; j < 8; j++) acc[i][j] = 0.f;

    const float* Aptr = X + (size_t)(bm + lr) * K + lc;
    const float* Bptr = W + (size_t)wr * N + bn + wc;

    for (int k0 = 0; k0 < K; k0 += 8) {
        float4 av = *reinterpret_cast<const float4*>(Aptr + k0);
        As[lc + 0][lr] = av.x; As[lc + 1][lr] = av.y;
        As[lc + 2][lr] = av.z; As[lc + 3][lr] = av.w;
        float4 bv = *reinterpret_cast<const float4*>(Bptr + (size_t)k0 * N);
        *reinterpret_cast<float4*>(&Bs[wr][wc]) = bv;
        __syncthreads();

        #pragma unroll
        for (int kk = 0; kk < 8; kk++) {
            float a[8], b[8];
            *(float4*)&a[0] = *(const float4*)&As[kk][trow];
            *(float4*)&a[4] = *(const float4*)&As[kk][trow + 4];
            *(float4*)&b[0] = *(const float4*)&Bs[kk][tcol];
            *(float4*)&b[4] = *(const float4*)&Bs[kk][tcol + 4];
            #pragma unroll
            for (int i = 0; i < 8; i++)
                #pragma unroll
                for (int j = 0; j < 8; j++)
                    acc[i][j] = fmaf(a[i], b[j], acc[i][j]);
        }
        __syncthreads();
    }

    #pragma unroll
    for (int i = 0; i < 8; i++) {
        size_t row = (size_t)(bm + trow + i);
        float* yrow = Y + row * N + bn + tcol;
        const float* rrow = (EPI == 2) ? (Res + row * N + bn + tcol) : nullptr;
        #pragma unroll
        for (int j = 0; j < 8; j += 4) {
            float4 bsv = *reinterpret_cast<const float4*>(bias + bn + tcol + j);
            float4 o;
            o.x = acc[i][j + 0] + bsv.x;
            o.y = acc[i][j + 1] + bsv.y;
            o.z = acc[i][j + 2] + bsv.z;
            o.w = acc[i][j + 3] + bsv.w;
            if (EPI == 1) {
                o.x = o.x >= 0.f ? o.x : 0.1f * o.x;
                o.y = o.y >= 0.f ? o.y : 0.1f * o.y;
                o.z = o.z >= 0.f ? o.z : 0.1f * o.z;
                o.w = o.w >= 0.f ? o.w : 0.1f * o.w;
            }
            if (EPI == 2) {
                float4 rv = *reinterpret_cast<const float4*>(rrow + j);
                o.x += rv.x; o.y += rv.y; o.z += rv.z; o.w += rv.w;
            }
            *reinterpret_cast<float4*>(yrow + j) = o;
        }
    }
}

// ---------------------------------------------------------------------------
// Flash-attention (fp32, online softmax). One block = one (b,h,q-tile of 64).
// ---------------------------------------------------------------------------
#define ASTRIDE 68
#define AARR (64 * ASTRIDE)
#define ATTN_SMEM (3 * AARR * sizeof(float))

__global__ __launch_bounds__(256) void attn_kernel(
    const float* __restrict__ Q, const float* __restrict__ K,
    const float* __restrict__ V, float* __restrict__ O)
{
    extern __shared__ float smem[];
    float* QPs = smem;               // Q staging, then P tile
    float* Ks  = smem + AARR;
    float* Vs  = smem + 2 * AARR;

    int qt = blockIdx.x;             // q tile (0..31)
    int bh = blockIdx.y;             // 0..63
    int b  = bh >> 4;
    int h  = bh & 15;
    const size_t base = (size_t)b * NSEQ * CDIM + (size_t)h * DHEAD;

    int tid = threadIdx.x;
    int row = tid >> 2;              // 0..63
    int g   = tid & 3;               // 0..3
    int cg  = g * 16;                // col-block start

    // ---- load Q tile into smem, then hoist this thread's row into regs ----
    for (int i = tid; i < 64 * 16; i += 256) {
        int r = i >> 4, c4 = i & 15;
        ((float4*)(QPs + r * ASTRIDE))[c4] =
            *(const float4*)(Q + base + (size_t)(qt * 64 + r) * CDIM + c4 * 4);
    }
    __syncthreads();
    float4 qreg[16];
    #pragma unroll
    for (int d4 = 0; d4 < 16; d4++)
        qreg[d4] = ((const float4*)(QPs + row * ASTRIDE))[d4];
    __syncthreads();   // QPs now free -> becomes Ps

    float m = -INFINITY, l = 0.f;
    float acc[16];
    #pragma unroll
    for (int i = 0; i < 16; i++) acc[i] = 0.f;

    const float scale = 0.125f;      // 64^-0.5

    for (int kt = 0; kt < NSEQ / 64; kt++) {
        __syncthreads();   // previous PV reads of Vs/Ps done
        // ---- load K,V tiles ----
        for (int i = tid; i < 64 * 16; i += 256) {
            int r = i >> 4, c4 = i & 15;
            size_t grow = base + (size_t)(kt * 64 + r) * CDIM + c4 * 4;
            ((float4*)(Ks + r * ASTRIDE))[c4] = *(const float4*)(K + grow);
            ((float4*)(Vs + r * ASTRIDE))[c4] = *(const float4*)(V + grow);
        }
        __syncthreads();

        // ---- S = Q K^T * scale  (staggered c order: bank-conflict free) ----
        float s[16];
        #pragma unroll
        for (int cc = 0; cc < 16; cc++) {
            int c = (cc + 4 * g) & 15;
            const float4* krow = (const float4*)(Ks + (cg + c) * ASTRIDE);
            float4 a4 = make_float4(0.f, 0.f, 0.f, 0.f);
            #pragma unroll
            for (int d4 = 0; d4 < 16; d4++) {
                float4 kv = krow[d4];
                a4.x = fmaf(qreg[d4].x, kv.x, a4.x);
                a4.y = fmaf(qreg[d4].y, kv.y, a4.y);
                a4.z = fmaf(qreg[d4].z, kv.z, a4.z);
                a4.w = fmaf(qreg[d4].w, kv.w, a4.w);
            }
            s[c] = (a4.x + a4.y + a4.z + a4.w) * scale;
        }

        // ---- online softmax ----
        float tmax = s[0];
        #pragma unroll
        for (int c = 1; c < 16; c++) tmax = fmaxf(tmax, s[c]);
        tmax = fmaxf(tmax, __shfl_xor_sync(0xffffffffu, tmax, 1));
        tmax = fmaxf(tmax, __shfl_xor_sync(0xffffffffu, tmax, 2));
        float mnew = fmaxf(m, tmax);
        float alpha = __expf(m - mnew);
        float rsum = 0.f;
        float p[16];
        #pragma unroll
        for (int c = 0; c < 16; c++) {
            p[c] = __expf(s[c] - mnew);
            rsum += p[c];
        }
        rsum += __shfl_xor_sync(0xffffffffu, rsum, 1);
        rsum += __shfl_xor_sync(0xffffffffu, rsum, 2);
        l = l * alpha + rsum;
        m = mnew;
        #pragma unroll
        for (int i = 0; i < 16; i++) acc[i] *= alpha;

        // ---- write P tile ----
        #pragma unroll
        for (int j = 0; j < 4; j++) {
            ((float4*)(QPs + row * ASTRIDE))[(cg >> 2) + j] =
                make_float4(p[4 * j], p[4 * j + 1], p[4 * j + 2], p[4 * j + 3]);
        }
        __syncthreads();

        // ---- acc += P @ V  (staggered j order for Vs reads) ----
        #pragma unroll
        for (int c4 = 0; c4 < 16; c4++) {
            float4 pv = ((const float4*)(QPs + row * ASTRIDE))[c4];
            float pe_[4] = {pv.x, pv.y, pv.z, pv.w};
            #pragma unroll
            for (int u = 0; u < 4; u++) {
                int c = 4 * c4 + u;
                float pp = pe_[u];
                const float4* vrow = (const float4*)(Vs + c * ASTRIDE);
                #pragma unroll
                for (int j = 0; j < 4; j++) {
                    int jj = (j + g) & 3;
                    float4 vv = vrow[(cg >> 2) + jj];
                    acc[4 * jj + 0] = fmaf(pp, vv.x, acc[4 * jj + 0]);
                    acc[4 * jj + 1] = fmaf(pp, vv.y, acc[4 * jj + 1]);
                    acc[4 * jj + 2] = fmaf(pp, vv.z, acc[4 * jj + 2]);
                    acc[4 * jj + 3] = fmaf(pp, vv.w, acc[4 * jj + 3]);
                }
            }
        }
    }

    // ---- normalize and write output ----
    float linv = 1.0f / l;
    float* orow = O + base + (size_t)(qt * 64 + row) * CDIM + cg;
    #pragma unroll
    for (int j = 0; j < 4; j++) {
        float4 o;
        o.x = acc[4 * j + 0] * linv;
        o.y = acc[4 * j + 1] * linv;
        o.z = acc[4 * j + 2] * linv;
        o.w = acc[4 * j + 3] * linv;
        *reinterpret_cast<float4*>(orow + 4 * j) = o;
    }
}

// ---------------------------------------------------------------------------
// Launch
// ---------------------------------------------------------------------------
extern "C" void kernel_launch(void* const* d_in, const int* in_sizes, int n_in,
                              void* d_out, int out_size)
{
    // setup_inputs() dict order:
    //  0:x 1:pos_embed 2:nq_g 3:nq_b 4:nk_g 5:nk_b 6:nv_g 7:nv_b 8:n_g 9:n_b
    //  10:wq 11:bq 12:wk 13:bk 14:wv 15:bv 16:wp 17:bp 18:w1 19:b1 20:w2 21:b2
    // Disambiguate against reference-signature order via in_sizes[8]:
    //  dict order  -> in_sizes[8] == 1024   (n_g)
    //  sig. order  -> in_sizes[8] == 1024*1024 (wq)
    bool dict_order = (in_sizes[8] == CDIM);

    const float* x   = (const float*)d_in[0];
    const float* pe  = (const float*)d_in[1];
    const float* nqg = (const float*)d_in[2];
    const float* nqb = (const float*)d_in[3];
    const float* nkg = (const float*)d_in[4];
    const float* nkb = (const float*)d_in[5];
    const float* nvg = (const float*)d_in[6];
    const float* nvb = (const float*)d_in[7];

    const float *ng, *nb, *wq, *bq, *wk, *bk, *wv, *bv, *wp, *bp,
                *w1, *b1, *w2, *b2;
    if (dict_order) {
        ng = (const float*)d_in[8];  nb = (const float*)d_in[9];
        wq = (const float*)d_in[10]; bq = (const float*)d_in[11];
        wk = (const float*)d_in[12]; bk = (const float*)d_in[13];
        wv = (const float*)d_in[14]; bv = (const float*)d_in[15];
        wp = (const float*)d_in[16]; bp = (const float*)d_in[17];
        w1 = (const float*)d_in[18]; b1 = (const float*)d_in[19];
        w2 = (const float*)d_in[20]; b2 = (const float*)d_in[21];
    } else {
        wq = (const float*)d_in[8];  bq = (const float*)d_in[9];
        wk = (const float*)d_in[10]; bk = (const float*)d_in[11];
        wv = (const float*)d_in[12]; bv = (const float*)d_in[13];
        wp = (const float*)d_in[14]; bp = (const float*)d_in[15];
        ng = (const float*)d_in[16]; nb = (const float*)d_in[17];
        w1 = (const float*)d_in[18]; b1 = (const float*)d_in[19];
        w2 = (const float*)d_in[20]; b2 = (const float*)d_in[21];
    }
    float* out = (float*)d_out;

    float* sc = nullptr;
    cudaGetSymbolAddress((void**)&sc, g_scratch);
    float* lnq = sc + 0 * SLAB;
    float* lnk = sc + 1 * SLAB;
    float* lnv = sc + 2 * SLAB;
    float* q   = sc + 3 * SLAB;
    float* k   = sc + 4 * SLAB;
    float* v   = sc + 5 * SLAB;
    float* ao  = sc + 6 * SLAB;
    float* hbuf= sc + 7 * SLAB;
    float* lnh = sc + 8 * SLAB;
    float* m1  = sc + 9 * SLAB;

    cudaFuncSetAttribute(attn_kernel,
                         cudaFuncAttributeMaxDynamicSharedMemorySize,
                         (int)ATTN_SMEM);

    // 1. LayerNorms for q/k/v paths
    ln_qkv_kernel<<<TOKENS, 256>>>(x, pe, nqg, nqb, nkg, nkb, nvg, nvb,
                                   lnq, lnk, lnv);

    // 2. QKV projections
    dim3 gC(CDIM / 128, TOKENS / 128);
    gemm_kernel<0><<<gC, 256>>>(lnq, wq, bq, nullptr, q, TOKENS, CDIM, CDIM);
    gemm_kernel<0><<<gC, 256>>>(lnk, wk, bk, nullptr, k, TOKENS, CDIM, CDIM);
    gemm_kernel<0><<<gC, 256>>>(lnv, wv, bv, nullptr, v, TOKENS, CDIM, CDIM);

    // 3. Attention
    dim3 gA(NSEQ / 64, 4 * NHEADS);
    attn_kernel<<<gA, 256, ATTN_SMEM>>>(q, k, v, ao);

    // 4. Output projection + residual (h = x + ao @ wp + bp)
    gemm_kernel<2><<<gC, 256>>>(ao, wp, bp, x, hbuf, TOKENS, CDIM, CDIM);

    // 5. LN(h)
    ln_kernel<<<TOKENS, 256>>>(hbuf, ng, nb, lnh);

    // 6. MLP1 + LeakyReLU
    dim3 gH(MLPH / 128, TOKENS / 128);
    gemm_kernel<1><<<gH, 256>>>(lnh, w1, b1, nullptr, m1, TOKENS, MLPH, CDIM);

    // 7. MLP2 + residual -> final output
    gemm_kernel<2><<<gC, 256>>>(m1, w2, b2, hbuf, out, TOKENS, CDIM, MLPH);
}

// round 5
// speedup vs baseline: 2.7989x; 2.7989x over previous
#include <cuda_runtime.h>
#include <math.h>

#define TOKENS 8192
#define NSEQ   2048
#define CDIM   1024
#define MLPH   4096
#define NHEADS 16
#define DHEAD  64
#define LN_EPS 1e-5f

#define SLAB 8388608ull
__device__ float g_scratch[9ull * SLAB + (unsigned long long)TOKENS * MLPH];

__device__ __forceinline__ float4 blockReduce4(float4 v) {
    __shared__ float4 red[8];
    #pragma unroll
    for (int o = 16; o > 0; o >>= 1) {
        v.x += __shfl_xor_sync(0xffffffffu, v.x, o);
        v.y += __shfl_xor_sync(0xffffffffu, v.y, o);
        v.z += __shfl_xor_sync(0xffffffffu, v.z, o);
        v.w += __shfl_xor_sync(0xffffffffu, v.w, o);
    }
    int w = threadIdx.x >> 5;
    if ((threadIdx.x & 31) == 0) red[w] = v;
    __syncthreads();
    v = red[threadIdx.x & 7];
    #pragma unroll
    for (int o = 4; o > 0; o >>= 1) {
        v.x += __shfl_xor_sync(0xffffffffu, v.x, o);
        v.y += __shfl_xor_sync(0xffffffffu, v.y, o);
        v.z += __shfl_xor_sync(0xffffffffu, v.z, o);
        v.w += __shfl_xor_sync(0xffffffffu, v.w, o);
    }
    return v;
}

__global__ __launch_bounds__(256) void ln_qkv_kernel(
    const float* __restrict__ x, const float* __restrict__ pe,
    const float* __restrict__ nqg, const float* __restrict__ nqb,
    const float* __restrict__ nkg, const float* __restrict__ nkb,
    const float* __restrict__ nvg, const float* __restrict__ nvb,
    float* __restrict__ lnq, float* __restrict__ lnk, float* __restrict__ lnv)
{
    int t = blockIdx.x;
    int n = t & (NSEQ - 1);
    int tid = threadIdx.x;

    const float4* xr = (const float4*)(x + (size_t)t * CDIM);
    const float4* pr = (const float4*)(pe + (size_t)n * CDIM);
    float4 xv = xr[tid];
    float4 pv = pr[tid];
    float4 xp = make_float4(xv.x + pv.x, xv.y + pv.y, xv.z + pv.z, xv.w + pv.w);

    float4 s;
    s.x = xv.x + xv.y + xv.z + xv.w;
    s.y = xv.x * xv.x + xv.y * xv.y + xv.z * xv.z + xv.w * xv.w;
    s.z = xp.x + xp.y + xp.z + xp.w;
    s.w = xp.x * xp.x + xp.y * xp.y + xp.z * xp.z + xp.w * xp.w;
    s = blockReduce4(s);

    const float inv = 1.0f / (float)CDIM;
    float m1 = s.x * inv, v1 = s.y * inv - m1 * m1;
    float r1 = rsqrtf(v1 + LN_EPS);
    float m2 = s.z * inv, v2 = s.w * inv - m2 * m2;
    float r2 = rsqrtf(v2 + LN_EPS);

    float4 g, b, o;
    size_t base = (size_t)t * CDIM;

    g = ((const float4*)nqg)[tid]; b = ((const float4*)nqb)[tid];
    o.x = (xv.x - m1) * r1 * g.x + b.x;
    o.y = (xv.y - m1) * r1 * g.y + b.y;
    o.z = (xv.z - m1) * r1 * g.z + b.z;
    o.w = (xv.w - m1) * r1 * g.w + b.w;
    ((float4*)(lnq + base))[tid] = o;

    float4 nrm;
    nrm.x = (xp.x - m2) * r2; nrm.y = (xp.y - m2) * r2;
    nrm.z = (xp.z - m2) * r2; nrm.w = (xp.w - m2) * r2;

    g = ((const float4*)nkg)[tid]; b = ((const float4*)nkb)[tid];
    o.x = nrm.x * g.x + b.x; o.y = nrm.y * g.y + b.y;
    o.z = nrm.z * g.z + b.z; o.w = nrm.w * g.w + b.w;
    ((float4*)(lnk + base))[tid] = o;

    g = ((const float4*)nvg)[tid]; b = ((const float4*)nvb)[tid];
    o.x = nrm.x * g.x + b.x; o.y = nrm.y * g.y + b.y;
    o.z = nrm.z * g.z + b.z; o.w = nrm.w * g.w + b.w;
    ((float4*)(lnv + base))[tid] = o;
}

__global__ __launch_bounds__(256) void ln_kernel(
    const float* __restrict__ in, const float* __restrict__ gg,
    const float* __restrict__ bb, float* __restrict__ out)
{
    int t = blockIdx.x;
    int tid = threadIdx.x;
    const float4* xr = (const float4*)(in + (size_t)t * CDIM);
    float4 xv = xr[tid];
    float4 s;
    s.x = xv.x + xv.y + xv.z + xv.w;
    s.y = xv.x * xv.x + xv.y * xv.y + xv.z * xv.z + xv.w * xv.w;
    s.z = 0.f; s.w = 0.f;
    s = blockReduce4(s);
    const float inv = 1.0f / (float)CDIM;
    float m = s.x * inv, v = s.y * inv - m * m;
    float r = rsqrtf(v + LN_EPS);
    float4 g = ((const float4*)gg)[tid];
    float4 b = ((const float4*)bb)[tid];
    float4 o;
    o.x = (xv.x - m) * r * g.x + b.x;
    o.y = (xv.y - m) * r * g.y + b.y;
    o.z = (xv.z - m) * r * g.z + b.z;
    o.w = (xv.w - m) * r * g.w + b.w;
    ((float4*)(out + (size_t)t * CDIM))[tid] = o;
}

template <int EPI>
__global__ __launch_bounds__(256) void gemm_kernel(
    const float* __restrict__ X, const float* __restrict__ W,
    const float* __restrict__ bias, const float* __restrict__ Res,
    float* __restrict__ Y, int M, int N, int K)
{
    __shared__ float As[8][128];
    __shared__ float Bs[8][128];

    int tid = threadIdx.x;
    int bm = blockIdx.y * 128;
    int bn = blockIdx.x * 128;

    int lr = tid >> 1;
    int lc = (tid & 1) * 4;
    int wr = tid >> 5;
    int wc = (tid & 31) * 4;

    int trow = (tid >> 4) * 8;
    int tcol = (tid & 15) * 8;

    float acc[8][8];
    #pragma unroll
    for (int i = 0; i < 8; i++)
        #pragma unroll
        for (int j = 0; j < 8; j++) acc[i][j] = 0.f;

    const float* Aptr = X + (size_t)(bm + lr) * K + lc;
    const float* Bptr = W + (size_t)wr * N + bn + wc;

    float4 av = *reinterpret_cast<const float4*>(Aptr);
    float4 bv = *reinterpret_cast<const float4*>(Bptr);

    for (int k0 = 0; k0 < K; k0 += 8) {
        As[lc + 0][lr] = av.x; As[lc + 1][lr] = av.y;
        As[lc + 2][lr] = av.z; As[lc + 3][lr] = av.w;
        *reinterpret_cast<float4*>(&Bs[wr][wc]) = bv;
        __syncthreads();

        if (k0 + 8 < K) {
            av = *reinterpret_cast<const float4*>(Aptr + k0 + 8);
            bv = *reinterpret_cast<const float4*>(Bptr + (size_t)(k0 + 8) * N);
        }

        #pragma unroll
        for (int kk = 0; kk < 8; kk++) {
            float a[8], b[8];
            *(float4*)&a[0] = *(const float4*)&As[kk][trow];
            *(float4*)&a[4] = *(const float4*)&As[kk][trow + 4];
            *(float4*)&b[0] = *(const float4*)&Bs[kk][tcol];
            *(float4*)&b[4] = *(const float4*)&Bs[kk][tcol + 4];
            #pragma unroll
            for (int i = 0; i < 8; i++)
                #pragma unroll
                for (int j = 0; j < 8; j++)
                    acc[i][j] = fmaf(a[i], b[j], acc[i][j]);
        }
        __syncthreads();
    }

    #pragma unroll
    for (int i = 0; i < 8; i++) {
        size_t row = (size_t)(bm + trow + i);
        float* yrow = Y + row * N + bn + tcol;
        const float* rrow = (EPI == 2) ? (Res + row * N + bn + tcol) : nullptr;
        #pragma unroll
        for (int j = 0; j < 8; j += 4) {
            float4 bsv = *reinterpret_cast<const float4*>(bias + bn + tcol + j);
            float4 o;
            o.x = acc[i][j + 0] + bsv.x;
            o.y = acc[i][j + 1] + bsv.y;
            o.z = acc[i][j + 2] + bsv.z;
            o.w = acc[i][j + 3] + bsv.w;
            if (EPI == 1) {
                o.x = o.x >= 0.f ? o.x : 0.1f * o.x;
                o.y = o.y >= 0.f ? o.y : 0.1f * o.y;
                o.z = o.z >= 0.f ? o.z : 0.1f * o.z;
                o.w = o.w >= 0.f ? o.w : 0.1f * o.w;
            }
            if (EPI == 2) {
                float4 rv = *reinterpret_cast<const float4*>(rrow + j);
                o.x += rv.x; o.y += rv.y; o.z += rv.z; o.w += rv.w;
            }
            *reinterpret_cast<float4*>(yrow + j) = o;
        }
    }
}

// ---------------------------------------------------------------------------
// Flash-attention, fully registerized (compile-time indices only).
// K tile chunk-swizzled (c4 ^ ((r>>4)&3)); qreg loaded pre-permuted by g so
// stored-position iteration pairs correctly without runtime register indexing.
// ---------------------------------------------------------------------------
#define ASTRIDE 68
#define AARR (64 * ASTRIDE)
#define ATTN_SMEM (3 * AARR * sizeof(float))

__global__ __launch_bounds__(256) void attn_kernel(
    const float* __restrict__ Q, const float* __restrict__ K,
    const float* __restrict__ V, float* __restrict__ O)
{
    extern __shared__ float smem[];
    float* QPs = smem;
    float* Ks  = smem + AARR;
    float* Vs  = smem + 2 * AARR;

    int qt = blockIdx.x;
    int bh = blockIdx.y;
    int b  = bh >> 4;
    int h  = bh & 15;
    const size_t base = (size_t)b * NSEQ * CDIM + (size_t)h * DHEAD;

    int tid = threadIdx.x;
    int row = tid >> 2;
    int g   = tid & 3;
    int cg  = g * 16;

    for (int i = tid; i < 64 * 16; i += 256) {
        int r = i >> 4, c4 = i & 15;
        ((float4*)(QPs + r * ASTRIDE))[c4] =
            *(const float4*)(Q + base + (size_t)(qt * 64 + r) * CDIM + c4 * 4);
    }
    __syncthreads();
    // qreg[d4] holds logical Q chunk (d4 ^ g) — matches K's stored positions.
    float4 qreg[16];
    #pragma unroll
    for (int d4 = 0; d4 < 16; d4++)
        qreg[d4] = ((const float4*)(QPs + row * ASTRIDE))[d4 ^ g];
    __syncthreads();

    float m = -INFINITY, l = 0.f;
    float acc[16];
    #pragma unroll
    for (int i = 0; i < 16; i++) acc[i] = 0.f;

    const float scale = 0.125f;

    for (int kt = 0; kt < NSEQ / 64; kt++) {
        __syncthreads();
        for (int i = tid; i < 64 * 16; i += 256) {
            int r = i >> 4, c4 = i & 15;
            size_t grow = base + (size_t)(kt * 64 + r) * CDIM + c4 * 4;
            int sw = c4 ^ ((r >> 4) & 3);
            ((float4*)(Ks + r * ASTRIDE))[sw] = *(const float4*)(K + grow);
            ((float4*)(Vs + r * ASTRIDE))[c4] = *(const float4*)(V + grow);
        }
        __syncthreads();

        float s[16];
        #pragma unroll
        for (int c = 0; c < 16; c++) {
            const float4* krow = (const float4*)(Ks + (cg + c) * ASTRIDE);
            float4 a4 = make_float4(0.f, 0.f, 0.f, 0.f);
            #pragma unroll
            for (int d4 = 0; d4 < 16; d4++) {
                float4 kv = krow[d4];     // stored pos d4 = logical chunk d4^g
                float4 qv = qreg[d4];     // logical chunk d4^g (pre-permuted)
                a4.x = fmaf(qv.x, kv.x, a4.x);
                a4.y = fmaf(qv.y, kv.y, a4.y);
                a4.z = fmaf(qv.z, kv.z, a4.z);
                a4.w = fmaf(qv.w, kv.w, a4.w);
            }
            s[c] = (a4.x + a4.y + a4.z + a4.w) * scale;
        }

        float tmax = s[0];
        #pragma unroll
        for (int c = 1; c < 16; c++) tmax = fmaxf(tmax, s[c]);
        tmax = fmaxf(tmax, __shfl_xor_sync(0xffffffffu, tmax, 1));
        tmax = fmaxf(tmax, __shfl_xor_sync(0xffffffffu, tmax, 2));
        float mnew = fmaxf(m, tmax);
        float alpha = __expf(m - mnew);
        float rsum = 0.f;
        float p[16];
        #pragma unroll
        for (int c = 0; c < 16; c++) {
            p[c] = __expf(s[c] - mnew);
            rsum += p[c];
        }
        rsum += __shfl_xor_sync(0xffffffffu, rsum, 1);
        rsum += __shfl_xor_sync(0xffffffffu, rsum, 2);
        l = l * alpha + rsum;
        m = mnew;
        #pragma unroll
        for (int i = 0; i < 16; i++) acc[i] *= alpha;

        #pragma unroll
        for (int j = 0; j < 4; j++) {
            ((float4*)(QPs + row * ASTRIDE))[4 * g + j] =
                make_float4(p[4 * j], p[4 * j + 1], p[4 * j + 2], p[4 * j + 3]);
        }
        __syncthreads();

        #pragma unroll
        for (int c4 = 0; c4 < 16; c4++) {
            float4 pv = ((const float4*)(QPs + row * ASTRIDE))[c4];
            const float* vb = Vs + (4 * c4) * ASTRIDE + cg;
            #pragma unroll
            for (int u = 0; u < 4; u++) {
                float pp = (u == 0) ? pv.x : (u == 1) ? pv.y : (u == 2) ? pv.z : pv.w;
                const float4* vrow = (const float4*)(vb + u * ASTRIDE);
                #pragma unroll
                for (int j = 0; j < 4; j++) {
                    float4 vv = vrow[j];
                    acc[4 * j + 0] = fmaf(pp, vv.x, acc[4 * j + 0]);
                    acc[4 * j + 1] = fmaf(pp, vv.y, acc[4 * j + 1]);
                    acc[4 * j + 2] = fmaf(pp, vv.z, acc[4 * j + 2]);
                    acc[4 * j + 3] = fmaf(pp, vv.w, acc[4 * j + 3]);
                }
            }
        }
    }

    float linv = 1.0f / l;
    float* orow = O + base + (size_t)(qt * 64 + row) * CDIM + cg;
    #pragma unroll
    for (int j = 0; j < 4; j++) {
        float4 o;
        o.x = acc[4 * j + 0] * linv;
        o.y = acc[4 * j + 1] * linv;
        o.z = acc[4 * j + 2] * linv;
        o.w = acc[4 * j + 3] * linv;
        *reinterpret_cast<float4*>(orow + 4 * j) = o;
    }
}

extern "C" void kernel_launch(void* const* d_in, const int* in_sizes, int n_in,
                              void* d_out, int out_size)
{
    bool dict_order = (in_sizes[8] == CDIM);

    const float* x   = (const float*)d_in[0];
    const float* pe  = (const float*)d_in[1];
    const float* nqg = (const float*)d_in[2];
    const float* nqb = (const float*)d_in[3];
    const float* nkg = (const float*)d_in[4];
    const float* nkb = (const float*)d_in[5];
    const float* nvg = (const float*)d_in[6];
    const float* nvb = (const float*)d_in[7];

    const float *ng, *nb, *wq, *bq, *wk, *bk, *wv, *bv, *wp, *bp,
                *w1, *b1, *w2, *b2;
    if (dict_order) {
        ng = (const float*)d_in[8];  nb = (const float*)d_in[9];
        wq = (const float*)d_in[10]; bq = (const float*)d_in[11];
        wk = (const float*)d_in[12]; bk = (const float*)d_in[13];
        wv = (const float*)d_in[14]; bv = (const float*)d_in[15];
        wp = (const float*)d_in[16]; bp = (const float*)d_in[17];
        w1 = (const float*)d_in[18]; b1 = (const float*)d_in[19];
        w2 = (const float*)d_in[20]; b2 = (const float*)d_in[21];
    } else {
        wq = (const float*)d_in[8];  bq = (const float*)d_in[9];
        wk = (const float*)d_in[10]; bk = (const float*)d_in[11];
        wv = (const float*)d_in[12]; bv = (const float*)d_in[13];
        wp = (const float*)d_in[14]; bp = (const float*)d_in[15];
        ng = (const float*)d_in[16]; nb = (const float*)d_in[17];
        w1 = (const float*)d_in[18]; b1 = (const float*)d_in[19];
        w2 = (const float*)d_in[20]; b2 = (const float*)d_in[21];
    }
    float* out = (float*)d_out;

    float* sc = nullptr;
    cudaGetSymbolAddress((void**)&sc, g_scratch);
    float* lnq = sc + 0 * SLAB;
    float* lnk = sc + 1 * SLAB;
    float* lnv = sc + 2 * SLAB;
    float* q   = sc + 3 * SLAB;
    float* k   = sc + 4 * SLAB;
    float* v   = sc + 5 * SLAB;
    float* ao  = sc + 6 * SLAB;
    float* hbuf= sc + 7 * SLAB;
    float* lnh = sc + 8 * SLAB;
    float* m1  = sc + 9 * SLAB;

    cudaFuncSetAttribute(attn_kernel,
                         cudaFuncAttributeMaxDynamicSharedMemorySize,
                         (int)ATTN_SMEM);

    ln_qkv_kernel<<<TOKENS, 256>>>(x, pe, nqg, nqb, nkg, nkb, nvg, nvb,
                                   lnq, lnk, lnv);

    dim3 gC(CDIM / 128, TOKENS / 128);
    gemm_kernel<0><<<gC, 256>>>(lnq, wq, bq, nullptr, q, TOKENS, CDIM, CDIM);
    gemm_kernel<0><<<gC, 256>>>(lnk, wk, bk, nullptr, k, TOKENS, CDIM, CDIM);
    gemm_kernel<0><<<gC, 256>>>(lnv, wv, bv, nullptr, v, TOKENS, CDIM, CDIM);

    dim3 gA(NSEQ / 64, 4 * NHEADS);
    attn_kernel<<<gA, 256, ATTN_SMEM>>>(q, k, v, ao);

    gemm_kernel<2><<<gC, 256>>>(ao, wp, bp, x, hbuf, TOKENS, CDIM, CDIM);

    ln_kernel<<<TOKENS, 256>>>(hbuf, ng, nb, lnh);

    dim3 gH(MLPH / 128, TOKENS / 128);
    gemm_kernel<1><<<gH, 256>>>(lnh, w1, b1, nullptr, m1, TOKENS, MLPH, CDIM);

    gemm_kernel<2><<<gC, 256>>>(m1, w2, b2, hbuf, out, TOKENS, CDIM, MLPH);
}

// round 6
// speedup vs baseline: 6.8017x; 2.4302x over previous
#include <cuda_runtime.h>
#include <math.h>

#define TOKENS 8192
#define NSEQ   2048
#define CDIM   1024
#define MLPH   4096
#define NHEADS 16
#define DHEAD  64
#define LN_EPS 1e-5f

#define SLAB 8388608ull
__device__ float g_scratch[9ull * SLAB + (unsigned long long)TOKENS * MLPH];

__device__ __forceinline__ float4 blockReduce4(float4 v) {
    __shared__ float4 red[8];
    #pragma unroll
    for (int o = 16; o > 0; o >>= 1) {
        v.x += __shfl_xor_sync(0xffffffffu, v.x, o);
        v.y += __shfl_xor_sync(0xffffffffu, v.y, o);
        v.z += __shfl_xor_sync(0xffffffffu, v.z, o);
        v.w += __shfl_xor_sync(0xffffffffu, v.w, o);
    }
    int w = threadIdx.x >> 5;
    if ((threadIdx.x & 31) == 0) red[w] = v;
    __syncthreads();
    v = red[threadIdx.x & 7];
    #pragma unroll
    for (int o = 4; o > 0; o >>= 1) {
        v.x += __shfl_xor_sync(0xffffffffu, v.x, o);
        v.y += __shfl_xor_sync(0xffffffffu, v.y, o);
        v.z += __shfl_xor_sync(0xffffffffu, v.z, o);
        v.w += __shfl_xor_sync(0xffffffffu, v.w, o);
    }
    return v;
}

__global__ __launch_bounds__(256) void ln_qkv_kernel(
    const float* __restrict__ x, const float* __restrict__ pe,
    const float* __restrict__ nqg, const float* __restrict__ nqb,
    const float* __restrict__ nkg, const float* __restrict__ nkb,
    const float* __restrict__ nvg, const float* __restrict__ nvb,
    float* __restrict__ lnq, float* __restrict__ lnk, float* __restrict__ lnv)
{
    int t = blockIdx.x;
    int n = t & (NSEQ - 1);
    int tid = threadIdx.x;

    const float4* xr = (const float4*)(x + (size_t)t * CDIM);
    const float4* pr = (const float4*)(pe + (size_t)n * CDIM);
    float4 xv = xr[tid];
    float4 pv = pr[tid];
    float4 xp = make_float4(xv.x + pv.x, xv.y + pv.y, xv.z + pv.z, xv.w + pv.w);

    float4 s;
    s.x = xv.x + xv.y + xv.z + xv.w;
    s.y = xv.x * xv.x + xv.y * xv.y + xv.z * xv.z + xv.w * xv.w;
    s.z = xp.x + xp.y + xp.z + xp.w;
    s.w = xp.x * xp.x + xp.y * xp.y + xp.z * xp.z + xp.w * xp.w;
    s = blockReduce4(s);

    const float inv = 1.0f / (float)CDIM;
    float m1 = s.x * inv, v1 = s.y * inv - m1 * m1;
    float r1 = rsqrtf(v1 + LN_EPS);
    float m2 = s.z * inv, v2 = s.w * inv - m2 * m2;
    float r2 = rsqrtf(v2 + LN_EPS);

    float4 g, b, o;
    size_t base = (size_t)t * CDIM;

    g = ((const float4*)nqg)[tid]; b = ((const float4*)nqb)[tid];
    o.x = (xv.x - m1) * r1 * g.x + b.x;
    o.y = (xv.y - m1) * r1 * g.y + b.y;
    o.z = (xv.z - m1) * r1 * g.z + b.z;
    o.w = (xv.w - m1) * r1 * g.w + b.w;
    ((float4*)(lnq + base))[tid] = o;

    float4 nrm;
    nrm.x = (xp.x - m2) * r2; nrm.y = (xp.y - m2) * r2;
    nrm.z = (xp.z - m2) * r2; nrm.w = (xp.w - m2) * r2;

    g = ((const float4*)nkg)[tid]; b = ((const float4*)nkb)[tid];
    o.x = nrm.x * g.x + b.x; o.y = nrm.y * g.y + b.y;
    o.z = nrm.z * g.z + b.z; o.w = nrm.w * g.w + b.w;
    ((float4*)(lnk + base))[tid] = o;

    g = ((const float4*)nvg)[tid]; b = ((const float4*)nvb)[tid];
    o.x = nrm.x * g.x + b.x; o.y = nrm.y * g.y + b.y;
    o.z = nrm.z * g.z + b.z; o.w = nrm.w * g.w + b.w;
    ((float4*)(lnv + base))[tid] = o;
}

__global__ __launch_bounds__(256) void ln_kernel(
    const float* __restrict__ in, const float* __restrict__ gg,
    const float* __restrict__ bb, float* __restrict__ out)
{
    int t = blockIdx.x;
    int tid = threadIdx.x;
    const float4* xr = (const float4*)(in + (size_t)t * CDIM);
    float4 xv = xr[tid];
    float4 s;
    s.x = xv.x + xv.y + xv.z + xv.w;
    s.y = xv.x * xv.x + xv.y * xv.y + xv.z * xv.z + xv.w * xv.w;
    s.z = 0.f; s.w = 0.f;
    s = blockReduce4(s);
    const float inv = 1.0f / (float)CDIM;
    float m = s.x * inv, v = s.y * inv - m * m;
    float r = rsqrtf(v + LN_EPS);
    float4 g = ((const float4*)gg)[tid];
    float4 b = ((const float4*)bb)[tid];
    float4 o;
    o.x = (xv.x - m) * r * g.x + b.x;
    o.y = (xv.y - m) * r * g.y + b.y;
    o.z = (xv.z - m) * r * g.z + b.z;
    o.w = (xv.w - m) * r * g.w + b.w;
    ((float4*)(out + (size_t)t * CDIM))[tid] = o;
}

// ---------------------------------------------------------------------------
// Tiled fp32 GEMM: 128x128x8, 256 thr, 8x8 microtile, reg-prefetch dbuf.
// EPI: 0 = bias ; 1 = bias + LeakyReLU ; 2 = bias + residual ;
//      3 = bias + TRANSPOSED store:  Y is [N][M], Y[col][row] = acc + bias[col]
// ---------------------------------------------------------------------------
template <int EPI>
__global__ __launch_bounds__(256) void gemm_kernel(
    const float* __restrict__ X, const float* __restrict__ W,
    const float* __restrict__ bias, const float* __restrict__ Res,
    float* __restrict__ Y, int M, int N, int K)
{
    __shared__ float As[8][128];
    __shared__ float Bs[8][128];

    int tid = threadIdx.x;
    int bm = blockIdx.y * 128;
    int bn = blockIdx.x * 128;

    int lr = tid >> 1;
    int lc = (tid & 1) * 4;
    int wr = tid >> 5;
    int wc = (tid & 31) * 4;

    int trow = (tid >> 4) * 8;
    int tcol = (tid & 15) * 8;

    float acc[8][8];
    #pragma unroll
    for (int i = 0; i < 8; i++)
        #pragma unroll
        for (int j = 0; j < 8; j++) acc[i][j] = 0.f;

    const float* Aptr = X + (size_t)(bm + lr) * K + lc;
    const float* Bptr = W + (size_t)wr * N + bn + wc;

    float4 av = *reinterpret_cast<const float4*>(Aptr);
    float4 bv = *reinterpret_cast<const float4*>(Bptr);

    for (int k0 = 0; k0 < K; k0 += 8) {
        As[lc + 0][lr] = av.x; As[lc + 1][lr] = av.y;
        As[lc + 2][lr] = av.z; As[lc + 3][lr] = av.w;
        *reinterpret_cast<float4*>(&Bs[wr][wc]) = bv;
        __syncthreads();

        if (k0 + 8 < K) {
            av = *reinterpret_cast<const float4*>(Aptr + k0 + 8);
            bv = *reinterpret_cast<const float4*>(Bptr + (size_t)(k0 + 8) * N);
        }

        #pragma unroll
        for (int kk = 0; kk < 8; kk++) {
            float a[8], b[8];
            *(float4*)&a[0] = *(const float4*)&As[kk][trow];
            *(float4*)&a[4] = *(const float4*)&As[kk][trow + 4];
            *(float4*)&b[0] = *(const float4*)&Bs[kk][tcol];
            *(float4*)&b[4] = *(const float4*)&Bs[kk][tcol + 4];
            #pragma unroll
            for (int i = 0; i < 8; i++)
                #pragma unroll
                for (int j = 0; j < 8; j++)
                    acc[i][j] = fmaf(a[i], b[j], acc[i][j]);
        }
        __syncthreads();
    }

    if (EPI == 3) {
        // transposed store into Y[N][M]
        #pragma unroll
        for (int j = 0; j < 8; j++) {
            int col = bn + tcol + j;
            float bsv = bias[col];
            float* ycol = Y + (size_t)col * M + bm + trow;
            float4 o0 = make_float4(acc[0][j] + bsv, acc[1][j] + bsv,
                                    acc[2][j] + bsv, acc[3][j] + bsv);
            float4 o1 = make_float4(acc[4][j] + bsv, acc[5][j] + bsv,
                                    acc[6][j] + bsv, acc[7][j] + bsv);
            *reinterpret_cast<float4*>(ycol) = o0;
            *reinterpret_cast<float4*>(ycol + 4) = o1;
        }
        return;
    }

    #pragma unroll
    for (int i = 0; i < 8; i++) {
        size_t row = (size_t)(bm + trow + i);
        float* yrow = Y + row * N + bn + tcol;
        const float* rrow = (EPI == 2) ? (Res + row * N + bn + tcol) : nullptr;
        #pragma unroll
        for (int j = 0; j < 8; j += 4) {
            float4 bsv = *reinterpret_cast<const float4*>(bias + bn + tcol + j);
            float4 o;
            o.x = acc[i][j + 0] + bsv.x;
            o.y = acc[i][j + 1] + bsv.y;
            o.z = acc[i][j + 2] + bsv.z;
            o.w = acc[i][j + 3] + bsv.w;
            if (EPI == 1) {
                o.x = o.x >= 0.f ? o.x : 0.1f * o.x;
                o.y = o.y >= 0.f ? o.y : 0.1f * o.y;
                o.z = o.z >= 0.f ? o.z : 0.1f * o.z;
                o.w = o.w >= 0.f ? o.w : 0.1f * o.w;
            }
            if (EPI == 2) {
                float4 rv = *reinterpret_cast<const float4*>(rrow + j);
                o.x += rv.x; o.y += rv.y; o.z += rv.z; o.w += rv.w;
            }
            *reinterpret_cast<float4*>(yrow + j) = o;
        }
    }
}

// ---------------------------------------------------------------------------
// Flash-attention v2: GEMM-style 8x8 microtiles.
// Q-tile 128 x K-tile 128, 256 threads (16x16 grid), d = 64.
// QT/KT are transposed [CDIM][TOKENS] (written by EPI=3 GEMM).
// smem: Qs[64][128], Ks[64][128], Vs[128][64], Pt[128][128] (XOR-swizzled).
// ---------------------------------------------------------------------------
#define ATT_SMEM_BYTES ((8192 * 3 + 16384) * 4)

__global__ __launch_bounds__(256) void attn2_kernel(
    const float* __restrict__ QT, const float* __restrict__ KT,
    const float* __restrict__ V, float* __restrict__ O)
{
    extern __shared__ float sm[];
    float* Qs = sm;             // [d][q]  stride 128
    float* Ks = sm + 8192;      // [d][k]  stride 128
    float* Vs = sm + 16384;     // [k][d]  stride 64
    float* Pt = sm + 24576;     // [k][q]  stride 128, chunk ^ ((k>>3)&7)

    int qt = blockIdx.x;        // 0..15
    int bh = blockIdx.y;        // 0..63
    int b = bh >> 4, h = bh & 15;

    int tid = threadIdx.x;
    int tx = tid & 15, ty = tid >> 4;
    int trow = ty * 8;          // q rows of this thread
    int tcol = tx * 8;          // k cols (S phase)
    int tdv  = tx * 4;          // d cols (PV phase)

    const size_t tokbase = (size_t)b * NSEQ;
    const float* qtb = QT + (size_t)(h * DHEAD) * TOKENS + tokbase + (size_t)qt * 128;
    const float* ktb = KT + (size_t)(h * DHEAD) * TOKENS + tokbase;
    const float* vbg = V + tokbase * CDIM + h * DHEAD;

    const float scale = 0.125f;   // 64^-0.5, folded into Q

    // load Q tile (64 d-rows x 128 q), scaled
    for (int i = tid; i < 64 * 32; i += 256) {
        int d = i >> 5, c = i & 31;
        float4 qv = ((const float4*)(qtb + (size_t)d * TOKENS))[c];
        qv.x *= scale; qv.y *= scale; qv.z *= scale; qv.w *= scale;
        ((float4*)(Qs + d * 128))[c] = qv;
    }

    float m[8], l[8], acc[8][4];
    #pragma unroll
    for (int i = 0; i < 8; i++) {
        m[i] = -INFINITY; l[i] = 0.f;
        #pragma unroll
        for (int j = 0; j < 4; j++) acc[i][j] = 0.f;
    }

    for (int kt = 0; kt < NSEQ / 128; kt++) {
        __syncthreads();   // prior PV (Pt/Vs reads) done; Q writes covered
        // load K tile [64][128]
        for (int i = tid; i < 64 * 32; i += 256) {
            int d = i >> 5, c = i & 31;
            ((float4*)(Ks + d * 128))[c] =
                ((const float4*)(ktb + (size_t)d * TOKENS + (size_t)kt * 128))[c];
        }
        // load V tile [128][64]
        for (int i = tid; i < 128 * 16; i += 256) {
            int k = i >> 4, c = i & 15;
            ((float4*)(Vs + k * 64))[c] =
                ((const float4*)(vbg + (size_t)(kt * 128 + k) * CDIM))[c];
        }
        __syncthreads();

        // ---- S = (Q*scale)·K^T : 8x8 per thread over d=64 ----
        float s[8][8];
        #pragma unroll
        for (int i = 0; i < 8; i++)
            #pragma unroll
            for (int j = 0; j < 8; j++) s[i][j] = 0.f;

        #pragma unroll 8
        for (int d = 0; d < 64; d++) {
            float a[8], bb[8];
            *(float4*)&a[0]  = *(const float4*)(Qs + d * 128 + trow);
            *(float4*)&a[4]  = *(const float4*)(Qs + d * 128 + trow + 4);
            *(float4*)&bb[0] = *(const float4*)(Ks + d * 128 + tcol);
            *(float4*)&bb[4] = *(const float4*)(Ks + d * 128 + tcol + 4);
            #pragma unroll
            for (int i = 0; i < 8; i++)
                #pragma unroll
                for (int j = 0; j < 8; j++)
                    s[i][j] = fmaf(a[i], bb[j], s[i][j]);
        }

        // ---- online softmax (rows split over 16 col-threads) ----
        #pragma unroll
        for (int i = 0; i < 8; i++) {
            float rm = s[i][0];
            #pragma unroll
            for (int j = 1; j < 8; j++) rm = fmaxf(rm, s[i][j]);
            rm = fmaxf(rm, __shfl_xor_sync(0xffffffffu, rm, 1));
            rm = fmaxf(rm, __shfl_xor_sync(0xffffffffu, rm, 2));
            rm = fmaxf(rm, __shfl_xor_sync(0xffffffffu, rm, 4));
            rm = fmaxf(rm, __shfl_xor_sync(0xffffffffu, rm, 8));
            float mn = fmaxf(m[i], rm);
            float al = __expf(m[i] - mn);
            float rs = 0.f;
            #pragma unroll
            for (int j = 0; j < 8; j++) {
                s[i][j] = __expf(s[i][j] - mn);
                rs += s[i][j];
            }
            rs += __shfl_xor_sync(0xffffffffu, rs, 1);
            rs += __shfl_xor_sync(0xffffffffu, rs, 2);
            rs += __shfl_xor_sync(0xffffffffu, rs, 4);
            rs += __shfl_xor_sync(0xffffffffu, rs, 8);
            l[i] = l[i] * al + rs;
            m[i] = mn;
            #pragma unroll
            for (int j = 0; j < 4; j++) acc[i][j] *= al;
        }

        // ---- write P^T (swizzled, conflict-free) ----
        {
            int c0 = trow >> 2;
            #pragma unroll
            for (int j = 0; j < 8; j++) {
                int k = tcol + j;
                int key = (k >> 3) & 7;
                float* prow = Pt + k * 128;
                ((float4*)prow)[c0 ^ key] =
                    make_float4(s[0][j], s[1][j], s[2][j], s[3][j]);
                ((float4*)prow)[(c0 + 1) ^ key] =
                    make_float4(s[4][j], s[5][j], s[6][j], s[7][j]);
            }
        }
        __syncthreads();

        // ---- acc += P^T-block · V : 8 rows x 4 d-cols over k=128 ----
        {
            int c0 = trow >> 2;
            #pragma unroll 4
            for (int k = 0; k < 128; k++) {
                int key = (k >> 3) & 7;
                const float* prow = Pt + k * 128;
                float a[8];
                *(float4*)&a[0] = ((const float4*)prow)[c0 ^ key];
                *(float4*)&a[4] = ((const float4*)prow)[(c0 + 1) ^ key];
                float4 vv = *(const float4*)(Vs + k * 64 + tdv);
                #pragma unroll
                for (int i = 0; i < 8; i++) {
                    acc[i][0] = fmaf(a[i], vv.x, acc[i][0]);
                    acc[i][1] = fmaf(a[i], vv.y, acc[i][1]);
                    acc[i][2] = fmaf(a[i], vv.z, acc[i][2]);
                    acc[i][3] = fmaf(a[i], vv.w, acc[i][3]);
                }
            }
        }
    }

    // ---- normalize + write output [token][h*64 + d] ----
    #pragma unroll
    for (int i = 0; i < 8; i++) {
        float linv = 1.0f / l[i];
        float4 o = make_float4(acc[i][0] * linv, acc[i][1] * linv,
                               acc[i][2] * linv, acc[i][3] * linv);
        size_t tok = tokbase + (size_t)qt * 128 + trow + i;
        *reinterpret_cast<float4*>(
            (float*)O + tok * CDIM + h * DHEAD + tdv) = o;
    }
}

extern "C" void kernel_launch(void* const* d_in, const int* in_sizes, int n_in,
                              void* d_out, int out_size)
{
    bool dict_order = (in_sizes[8] == CDIM);

    const float* x   = (const float*)d_in[0];
    const float* pe  = (const float*)d_in[1];
    const float* nqg = (const float*)d_in[2];
    const float* nqb = (const float*)d_in[3];
    const float* nkg = (const float*)d_in[4];
    const float* nkb = (const float*)d_in[5];
    const float* nvg = (const float*)d_in[6];
    const float* nvb = (const float*)d_in[7];

    const float *ng, *nb, *wq, *bq, *wk, *bk, *wv, *bv, *wp, *bp,
                *w1, *b1, *w2, *b2;
    if (dict_order) {
        ng = (const float*)d_in[8];  nb = (const float*)d_in[9];
        wq = (const float*)d_in[10]; bq = (const float*)d_in[11];
        wk = (const float*)d_in[12]; bk = (const float*)d_in[13];
        wv = (const float*)d_in[14]; bv = (const float*)d_in[15];
        wp = (const float*)d_in[16]; bp = (const float*)d_in[17];
        w1 = (const float*)d_in[18]; b1 = (const float*)d_in[19];
        w2 = (const float*)d_in[20]; b2 = (const float*)d_in[21];
    } else {
        wq = (const float*)d_in[8];  bq = (const float*)d_in[9];
        wk = (const float*)d_in[10]; bk = (const float*)d_in[11];
        wv = (const float*)d_in[12]; bv = (const float*)d_in[13];
        wp = (const float*)d_in[14]; bp = (const float*)d_in[15];
        ng = (const float*)d_in[16]; nb = (const float*)d_in[17];
        w1 = (const float*)d_in[18]; b1 = (const float*)d_in[19];
        w2 = (const float*)d_in[20]; b2 = (const float*)d_in[21];
    }
    float* out = (float*)d_out;

    float* sc = nullptr;
    cudaGetSymbolAddress((void**)&sc, g_scratch);
    float* lnq = sc + 0 * SLAB;
    float* lnk = sc + 1 * SLAB;
    float* lnv = sc + 2 * SLAB;
    float* qT  = sc + 3 * SLAB;   // [CDIM][TOKENS]
    float* kT  = sc + 4 * SLAB;   // [CDIM][TOKENS]
    float* v   = sc + 5 * SLAB;   // [TOKENS][CDIM]
    float* ao  = sc + 6 * SLAB;
    float* hbuf= sc + 7 * SLAB;
    float* lnh = sc + 8 * SLAB;
    float* m1  = sc + 9 * SLAB;

    cudaFuncSetAttribute(attn2_kernel,
                         cudaFuncAttributeMaxDynamicSharedMemorySize,
                         ATT_SMEM_BYTES);

    ln_qkv_kernel<<<TOKENS, 256>>>(x, pe, nqg, nqb, nkg, nkb, nvg, nvb,
                                   lnq, lnk, lnv);

    dim3 gC(CDIM / 128, TOKENS / 128);
    // Q and K projections with TRANSPOSED output (for attention d-major access)
    gemm_kernel<3><<<gC, 256>>>(lnq, wq, bq, nullptr, qT, TOKENS, CDIM, CDIM);
    gemm_kernel<3><<<gC, 256>>>(lnk, wk, bk, nullptr, kT, TOKENS, CDIM, CDIM);
    gemm_kernel<0><<<gC, 256>>>(lnv, wv, bv, nullptr, v,  TOKENS, CDIM, CDIM);

    dim3 gA(NSEQ / 128, 4 * NHEADS);
    attn2_kernel<<<gA, 256, ATT_SMEM_BYTES>>>(qT, kT, v, ao);

    gemm_kernel<2><<<gC, 256>>>(ao, wp, bp, x, hbuf, TOKENS, CDIM, CDIM);

    ln_kernel<<<TOKENS, 256>>>(hbuf, ng, nb, lnh);

    dim3 gH(MLPH / 128, TOKENS / 128);
    gemm_kernel<1><<<gH, 256>>>(lnh, w1, b1, nullptr, m1, TOKENS, MLPH, CDIM);

    gemm_kernel<2><<<gC, 256>>>(m1, w2, b2, hbuf, out, TOKENS, CDIM, MLPH);
}

// round 7
// speedup vs baseline: 11.6836x; 1.7177x over previous
#include <cuda_runtime.h>
#include <math.h>

#define TOKENS 8192
#define NSEQ   2048
#define CDIM   1024
#define MLPH   4096
#define NHEADS 16
#define DHEAD  64
#define LN_EPS 1e-5f

#define SLAB 8388608ull
__device__ float g_scratch[9ull * SLAB + (unsigned long long)TOKENS * MLPH];

__device__ __forceinline__ float4 blockReduce4(float4 v) {
    __shared__ float4 red[8];
    #pragma unroll
    for (int o = 16; o > 0; o >>= 1) {
        v.x += __shfl_xor_sync(0xffffffffu, v.x, o);
        v.y += __shfl_xor_sync(0xffffffffu, v.y, o);
        v.z += __shfl_xor_sync(0xffffffffu, v.z, o);
        v.w += __shfl_xor_sync(0xffffffffu, v.w, o);
    }
    int w = threadIdx.x >> 5;
    if ((threadIdx.x & 31) == 0) red[w] = v;
    __syncthreads();
    v = red[threadIdx.x & 7];
    #pragma unroll
    for (int o = 4; o > 0; o >>= 1) {
        v.x += __shfl_xor_sync(0xffffffffu, v.x, o);
        v.y += __shfl_xor_sync(0xffffffffu, v.y, o);
        v.z += __shfl_xor_sync(0xffffffffu, v.z, o);
        v.w += __shfl_xor_sync(0xffffffffu, v.w, o);
    }
    return v;
}

__global__ __launch_bounds__(256) void ln_qkv_kernel(
    const float* __restrict__ x, const float* __restrict__ pe,
    const float* __restrict__ nqg, const float* __restrict__ nqb,
    const float* __restrict__ nkg, const float* __restrict__ nkb,
    const float* __restrict__ nvg, const float* __restrict__ nvb,
    float* __restrict__ lnq, float* __restrict__ lnk, float* __restrict__ lnv)
{
    int t = blockIdx.x;
    int n = t & (NSEQ - 1);
    int tid = threadIdx.x;

    const float4* xr = (const float4*)(x + (size_t)t * CDIM);
    const float4* pr = (const float4*)(pe + (size_t)n * CDIM);
    float4 xv = xr[tid];
    float4 pv = pr[tid];
    float4 xp = make_float4(xv.x + pv.x, xv.y + pv.y, xv.z + pv.z, xv.w + pv.w);

    float4 s;
    s.x = xv.x + xv.y + xv.z + xv.w;
    s.y = xv.x * xv.x + xv.y * xv.y + xv.z * xv.z + xv.w * xv.w;
    s.z = xp.x + xp.y + xp.z + xp.w;
    s.w = xp.x * xp.x + xp.y * xp.y + xp.z * xp.z + xp.w * xp.w;
    s = blockReduce4(s);

    const float inv = 1.0f / (float)CDIM;
    float m1 = s.x * inv, v1 = s.y * inv - m1 * m1;
    float r1 = rsqrtf(v1 + LN_EPS);
    float m2 = s.z * inv, v2 = s.w * inv - m2 * m2;
    float r2 = rsqrtf(v2 + LN_EPS);

    float4 g, b, o;
    size_t base = (size_t)t * CDIM;

    g = ((const float4*)nqg)[tid]; b = ((const float4*)nqb)[tid];
    o.x = (xv.x - m1) * r1 * g.x + b.x;
    o.y = (xv.y - m1) * r1 * g.y + b.y;
    o.z = (xv.z - m1) * r1 * g.z + b.z;
    o.w = (xv.w - m1) * r1 * g.w + b.w;
    ((float4*)(lnq + base))[tid] = o;

    float4 nrm;
    nrm.x = (xp.x - m2) * r2; nrm.y = (xp.y - m2) * r2;
    nrm.z = (xp.z - m2) * r2; nrm.w = (xp.w - m2) * r2;

    g = ((const float4*)nkg)[tid]; b = ((const float4*)nkb)[tid];
    o.x = nrm.x * g.x + b.x; o.y = nrm.y * g.y + b.y;
    o.z = nrm.z * g.z + b.z; o.w = nrm.w * g.w + b.w;
    ((float4*)(lnk + base))[tid] = o;

    g = ((const float4*)nvg)[tid]; b = ((const float4*)nvb)[tid];
    o.x = nrm.x * g.x + b.x; o.y = nrm.y * g.y + b.y;
    o.z = nrm.z * g.z + b.z; o.w = nrm.w * g.w + b.w;
    ((float4*)(lnv + base))[tid] = o;
}

__global__ __launch_bounds__(256) void ln_kernel(
    const float* __restrict__ in, const float* __restrict__ gg,
    const float* __restrict__ bb, float* __restrict__ out)
{
    int t = blockIdx.x;
    int tid = threadIdx.x;
    const float4* xr = (const float4*)(in + (size_t)t * CDIM);
    float4 xv = xr[tid];
    float4 s;
    s.x = xv.x + xv.y + xv.z + xv.w;
    s.y = xv.x * xv.x + xv.y * xv.y + xv.z * xv.z + xv.w * xv.w;
    s.z = 0.f; s.w = 0.f;
    s = blockReduce4(s);
    const float inv = 1.0f / (float)CDIM;
    float m = s.x * inv, v = s.y * inv - m * m;
    float r = rsqrtf(v + LN_EPS);
    float4 g = ((const float4*)gg)[tid];
    float4 b = ((const float4*)bb)[tid];
    float4 o;
    o.x = (xv.x - m) * r * g.x + b.x;
    o.y = (xv.y - m) * r * g.y + b.y;
    o.z = (xv.z - m) * r * g.z + b.z;
    o.w = (xv.w - m) * r * g.w + b.w;
    ((float4*)(out + (size_t)t * CDIM))[tid] = o;
}

// ---------------------------------------------------------------------------
// tf32 tensor-core helpers
// ---------------------------------------------------------------------------
__device__ __forceinline__ unsigned f2tf(float f) {
    unsigned u;
    asm("cvt.rna.tf32.f32 %0, %1;" : "=r"(u) : "f"(f));
    return u;
}

__device__ __forceinline__ void mma_tf32(float* d, const unsigned* a,
                                         const unsigned* b) {
    asm volatile(
        "mma.sync.aligned.m16n8k8.row.col.f32.tf32.tf32.f32 "
        "{%0,%1,%2,%3}, {%4,%5,%6,%7}, {%8,%9}, {%0,%1,%2,%3};\n"
        : "+f"(d[0]), "+f"(d[1]), "+f"(d[2]), "+f"(d[3])
        : "r"(a[0]), "r"(a[1]), "r"(a[2]), "r"(a[3]),
          "r"(b[0]), "r"(b[1]));
}

// ---------------------------------------------------------------------------
// tf32 GEMM: Y[M,N] = X[M,K] @ W[K,N] + bias. 128x128x16 tile, 256 thr,
// 8 warps (2x4), warp tile 64x32 via m16n8k8 mma.
// As[m][k] stride 20 (bank-perfect frag loads, 16B-aligned rows).
// Bs[k][n] stride 136 (bank-perfect frag loads).
// EPI: 0 bias ; 1 bias+LeakyReLU ; 2 bias+residual ; 3 bias+transposed store.
// ---------------------------------------------------------------------------
#define ASTR 20
#define BSTR 136

template <int EPI>
__global__ __launch_bounds__(256) void gemm_tf32_kernel(
    const float* __restrict__ X, const float* __restrict__ W,
    const float* __restrict__ bias, const float* __restrict__ Res,
    float* __restrict__ Y, int M, int N, int K)
{
    __shared__ unsigned As[128][ASTR];
    __shared__ unsigned Bs[16][BSTR];

    int tid = threadIdx.x;
    int bm = blockIdx.y * 128;
    int bn = blockIdx.x * 128;

    int warp = tid >> 5, lane = tid & 31;
    int wm = (warp & 1) * 64;       // warp m offset
    int wn = (warp >> 1) * 32;      // warp n offset
    int tg = lane & 3, gid = lane >> 2;

    // loader mapping
    int lr = tid >> 1;              // A row 0..127
    int lc = (tid & 1) * 8;         // A k base 0 or 8
    int kr = warp;                  // B k rows: warp, warp+8
    int nc = lane * 4;              // B n offset 0..124

    float acc[4][4][4];
    #pragma unroll
    for (int i = 0; i < 4; i++)
        #pragma unroll
        for (int j = 0; j < 4; j++)
            #pragma unroll
            for (int r = 0; r < 4; r++) acc[i][j][r] = 0.f;

    const float* Aptr = X + (size_t)(bm + lr) * K + lc;
    const float* Bptr = W + (size_t)kr * N + bn + nc;

    float4 a0v = *(const float4*)(Aptr);
    float4 a1v = *(const float4*)(Aptr + 4);
    float4 b0v = *(const float4*)(Bptr);
    float4 b1v = *(const float4*)(Bptr + (size_t)8 * N);

    for (int k0 = 0; k0 < K; k0 += 16) {
        // stage (cvt to tf32 at store time)
        *(uint4*)&As[lr][lc] =
            make_uint4(f2tf(a0v.x), f2tf(a0v.y), f2tf(a0v.z), f2tf(a0v.w));
        *(uint4*)&As[lr][lc + 4] =
            make_uint4(f2tf(a1v.x), f2tf(a1v.y), f2tf(a1v.z), f2tf(a1v.w));
        *(uint4*)&Bs[kr][nc] =
            make_uint4(f2tf(b0v.x), f2tf(b0v.y), f2tf(b0v.z), f2tf(b0v.w));
        *(uint4*)&Bs[kr + 8][nc] =
            make_uint4(f2tf(b1v.x), f2tf(b1v.y), f2tf(b1v.z), f2tf(b1v.w));
        __syncthreads();

        if (k0 + 16 < K) {
            a0v = *(const float4*)(Aptr + k0 + 16);
            a1v = *(const float4*)(Aptr + k0 + 20);
            b0v = *(const float4*)(Bptr + (size_t)(k0 + 16) * N);
            b1v = *(const float4*)(Bptr + (size_t)(k0 + 24) * N);
        }

        #pragma unroll
        for (int kk = 0; kk < 16; kk += 8) {
            unsigned af[4][4];
            #pragma unroll
            for (int mi = 0; mi < 4; mi++) {
                int r = wm + mi * 16 + gid;
                af[mi][0] = As[r][kk + tg];
                af[mi][1] = As[r + 8][kk + tg];
                af[mi][2] = As[r][kk + tg + 4];
                af[mi][3] = As[r + 8][kk + tg + 4];
            }
            unsigned bf[4][2];
            #pragma unroll
            for (int ni = 0; ni < 4; ni++) {
                int c = wn + ni * 8 + gid;
                bf[ni][0] = Bs[kk + tg][c];
                bf[ni][1] = Bs[kk + tg + 4][c];
            }
            #pragma unroll
            for (int mi = 0; mi < 4; mi++)
                #pragma unroll
                for (int ni = 0; ni < 4; ni++)
                    mma_tf32(acc[mi][ni], af[mi], bf[ni]);
        }
        __syncthreads();
    }

    // ---- epilogue ----
    if (EPI == 3) {
        #pragma unroll
        for (int mi = 0; mi < 4; mi++) {
            int r0 = bm + wm + mi * 16 + gid;
            int r1 = r0 + 8;
            #pragma unroll
            for (int ni = 0; ni < 4; ni++) {
                int col = bn + wn + ni * 8 + 2 * tg;
                float bs0 = bias[col], bs1 = bias[col + 1];
                Y[(size_t)col * M + r0]       = acc[mi][ni][0] + bs0;
                Y[(size_t)(col + 1) * M + r0] = acc[mi][ni][1] + bs1;
                Y[(size_t)col * M + r1]       = acc[mi][ni][2] + bs0;
                Y[(size_t)(col + 1) * M + r1] = acc[mi][ni][3] + bs1;
            }
        }
        return;
    }

    #pragma unroll
    for (int mi = 0; mi < 4; mi++) {
        int r0 = bm + wm + mi * 16 + gid;
        int r1 = r0 + 8;
        #pragma unroll
        for (int ni = 0; ni < 4; ni++) {
            int col = bn + wn + ni * 8 + 2 * tg;
            float2 bs = *(const float2*)(bias + col);
            float2 v0, v1;
            v0.x = acc[mi][ni][0] + bs.x;
            v0.y = acc[mi][ni][1] + bs.y;
            v1.x = acc[mi][ni][2] + bs.x;
            v1.y = acc[mi][ni][3] + bs.y;
            if (EPI == 1) {
                v0.x = v0.x >= 0.f ? v0.x : 0.1f * v0.x;
                v0.y = v0.y >= 0.f ? v0.y : 0.1f * v0.y;
                v1.x = v1.x >= 0.f ? v1.x : 0.1f * v1.x;
                v1.y = v1.y >= 0.f ? v1.y : 0.1f * v1.y;
            }
            if (EPI == 2) {
                float2 q0 = *(const float2*)(Res + (size_t)r0 * N + col);
                float2 q1 = *(const float2*)(Res + (size_t)r1 * N + col);
                v0.x += q0.x; v0.y += q0.y;
                v1.x += q1.x; v1.y += q1.y;
            }
            *(float2*)(Y + (size_t)r0 * N + col) = v0;
            *(float2*)(Y + (size_t)r1 * N + col) = v1;
        }
    }
}

// ---------------------------------------------------------------------------
// Flash-attention v2: GEMM-style 8x8 microtiles (unchanged from round 6).
// ---------------------------------------------------------------------------
#define ATT_SMEM_BYTES ((8192 * 3 + 16384) * 4)

__global__ __launch_bounds__(256) void attn2_kernel(
    const float* __restrict__ QT, const float* __restrict__ KT,
    const float* __restrict__ V, float* __restrict__ O)
{
    extern __shared__ float sm[];
    float* Qs = sm;             // [d][q]  stride 128
    float* Ks = sm + 8192;      // [d][k]  stride 128
    float* Vs = sm + 16384;     // [k][d]  stride 64
    float* Pt = sm + 24576;     // [k][q]  stride 128, chunk ^ ((k>>3)&7)

    int qt = blockIdx.x;
    int bh = blockIdx.y;
    int b = bh >> 4, h = bh & 15;

    int tid = threadIdx.x;
    int tx = tid & 15, ty = tid >> 4;
    int trow = ty * 8;
    int tcol = tx * 8;
    int tdv  = tx * 4;

    const size_t tokbase = (size_t)b * NSEQ;
    const float* qtb = QT + (size_t)(h * DHEAD) * TOKENS + tokbase + (size_t)qt * 128;
    const float* ktb = KT + (size_t)(h * DHEAD) * TOKENS + tokbase;
    const float* vbg = V + tokbase * CDIM + h * DHEAD;

    const float scale = 0.125f;

    for (int i = tid; i < 64 * 32; i += 256) {
        int d = i >> 5, c = i & 31;
        float4 qv = ((const float4*)(qtb + (size_t)d * TOKENS))[c];
        qv.x *= scale; qv.y *= scale; qv.z *= scale; qv.w *= scale;
        ((float4*)(Qs + d * 128))[c] = qv;
    }

    float m[8], l[8], acc[8][4];
    #pragma unroll
    for (int i = 0; i < 8; i++) {
        m[i] = -INFINITY; l[i] = 0.f;
        #pragma unroll
        for (int j = 0; j < 4; j++) acc[i][j] = 0.f;
    }

    for (int kt = 0; kt < NSEQ / 128; kt++) {
        __syncthreads();
        for (int i = tid; i < 64 * 32; i += 256) {
            int d = i >> 5, c = i & 31;
            ((float4*)(Ks + d * 128))[c] =
                ((const float4*)(ktb + (size_t)d * TOKENS + (size_t)kt * 128))[c];
        }
        for (int i = tid; i < 128 * 16; i += 256) {
            int k = i >> 4, c = i & 15;
            ((float4*)(Vs + k * 64))[c] =
                ((const float4*)(vbg + (size_t)(kt * 128 + k) * CDIM))[c];
        }
        __syncthreads();

        float s[8][8];
        #pragma unroll
        for (int i = 0; i < 8; i++)
            #pragma unroll
            for (int j = 0; j < 8; j++) s[i][j] = 0.f;

        #pragma unroll 8
        for (int d = 0; d < 64; d++) {
            float a[8], bb[8];
            *(float4*)&a[0]  = *(const float4*)(Qs + d * 128 + trow);
            *(float4*)&a[4]  = *(const float4*)(Qs + d * 128 + trow + 4);
            *(float4*)&bb[0] = *(const float4*)(Ks + d * 128 + tcol);
            *(float4*)&bb[4] = *(const float4*)(Ks + d * 128 + tcol + 4);
            #pragma unroll
            for (int i = 0; i < 8; i++)
                #pragma unroll
                for (int j = 0; j < 8; j++)
                    s[i][j] = fmaf(a[i], bb[j], s[i][j]);
        }

        #pragma unroll
        for (int i = 0; i < 8; i++) {
            float rm = s[i][0];
            #pragma unroll
            for (int j = 1; j < 8; j++) rm = fmaxf(rm, s[i][j]);
            rm = fmaxf(rm, __shfl_xor_sync(0xffffffffu, rm, 1));
            rm = fmaxf(rm, __shfl_xor_sync(0xffffffffu, rm, 2));
            rm = fmaxf(rm, __shfl_xor_sync(0xffffffffu, rm, 4));
            rm = fmaxf(rm, __shfl_xor_sync(0xffffffffu, rm, 8));
            float mn = fmaxf(m[i], rm);
            float al = __expf(m[i] - mn);
            float rs = 0.f;
            #pragma unroll
            for (int j = 0; j < 8; j++) {
                s[i][j] = __expf(s[i][j] - mn);
                rs += s[i][j];
            }
            rs += __shfl_xor_sync(0xffffffffu, rs, 1);
            rs += __shfl_xor_sync(0xffffffffu, rs, 2);
            rs += __shfl_xor_sync(0xffffffffu, rs, 4);
            rs += __shfl_xor_sync(0xffffffffu, rs, 8);
            l[i] = l[i] * al + rs;
            m[i] = mn;
            #pragma unroll
            for (int j = 0; j < 4; j++) acc[i][j] *= al;
        }

        {
            int c0 = trow >> 2;
            #pragma unroll
            for (int j = 0; j < 8; j++) {
                int k = tcol + j;
                int key = (k >> 3) & 7;
                float* prow = Pt + k * 128;
                ((float4*)prow)[c0 ^ key] =
                    make_float4(s[0][j], s[1][j], s[2][j], s[3][j]);
                ((float4*)prow)[(c0 + 1) ^ key] =
                    make_float4(s[4][j], s[5][j], s[6][j], s[7][j]);
            }
        }
        __syncthreads();

        {
            int c0 = trow >> 2;
            #pragma unroll 4
            for (int k = 0; k < 128; k++) {
                int key = (k >> 3) & 7;
                const float* prow = Pt + k * 128;
                float a[8];
                *(float4*)&a[0] = ((const float4*)prow)[c0 ^ key];
                *(float4*)&a[4] = ((const float4*)prow)[(c0 + 1) ^ key];
                float4 vv = *(const float4*)(Vs + k * 64 + tdv);
                #pragma unroll
                for (int i = 0; i < 8; i++) {
                    acc[i][0] = fmaf(a[i], vv.x, acc[i][0]);
                    acc[i][1] = fmaf(a[i], vv.y, acc[i][1]);
                    acc[i][2] = fmaf(a[i], vv.z, acc[i][2]);
                    acc[i][3] = fmaf(a[i], vv.w, acc[i][3]);
                }
            }
        }
    }

    #pragma unroll
    for (int i = 0; i < 8; i++) {
        float linv = 1.0f / l[i];
        float4 o = make_float4(acc[i][0] * linv, acc[i][1] * linv,
                               acc[i][2] * linv, acc[i][3] * linv);
        size_t tok = tokbase + (size_t)qt * 128 + trow + i;
        *reinterpret_cast<float4*>(
            (float*)O + tok * CDIM + h * DHEAD + tdv) = o;
    }
}

extern "C" void kernel_launch(void* const* d_in, const int* in_sizes, int n_in,
                              void* d_out, int out_size)
{
    bool dict_order = (in_sizes[8] == CDIM);

    const float* x   = (const float*)d_in[0];
    const float* pe  = (const float*)d_in[1];
    const float* nqg = (const float*)d_in[2];
    const float* nqb = (const float*)d_in[3];
    const float* nkg = (const float*)d_in[4];
    const float* nkb = (const float*)d_in[5];
    const float* nvg = (const float*)d_in[6];
    const float* nvb = (const float*)d_in[7];

    const float *ng, *nb, *wq, *bq, *wk, *bk, *wv, *bv, *wp, *bp,
                *w1, *b1, *w2, *b2;
    if (dict_order) {
        ng = (const float*)d_in[8];  nb = (const float*)d_in[9];
        wq = (const float*)d_in[10]; bq = (const float*)d_in[11];
        wk = (const float*)d_in[12]; bk = (const float*)d_in[13];
        wv = (const float*)d_in[14]; bv = (const float*)d_in[15];
        wp = (const float*)d_in[16]; bp = (const float*)d_in[17];
        w1 = (const float*)d_in[18]; b1 = (const float*)d_in[19];
        w2 = (const float*)d_in[20]; b2 = (const float*)d_in[21];
    } else {
        wq = (const float*)d_in[8];  bq = (const float*)d_in[9];
        wk = (const float*)d_in[10]; bk = (const float*)d_in[11];
        wv = (const float*)d_in[12]; bv = (const float*)d_in[13];
        wp = (const float*)d_in[14]; bp = (const float*)d_in[15];
        ng = (const float*)d_in[16]; nb = (const float*)d_in[17];
        w1 = (const float*)d_in[18]; b1 = (const float*)d_in[19];
        w2 = (const float*)d_in[20]; b2 = (const float*)d_in[21];
    }
    float* out = (float*)d_out;

    float* sc = nullptr;
    cudaGetSymbolAddress((void**)&sc, g_scratch);
    float* lnq = sc + 0 * SLAB;
    float* lnk = sc + 1 * SLAB;
    float* lnv = sc + 2 * SLAB;
    float* qT  = sc + 3 * SLAB;   // [CDIM][TOKENS]
    float* kT  = sc + 4 * SLAB;   // [CDIM][TOKENS]
    float* v   = sc + 5 * SLAB;   // [TOKENS][CDIM]
    float* ao  = sc + 6 * SLAB;
    float* hbuf= sc + 7 * SLAB;
    float* lnh = sc + 8 * SLAB;
    float* m1  = sc + 9 * SLAB;

    cudaFuncSetAttribute(attn2_kernel,
                         cudaFuncAttributeMaxDynamicSharedMemorySize,
                         ATT_SMEM_BYTES);

    ln_qkv_kernel<<<TOKENS, 256>>>(x, pe, nqg, nqb, nkg, nkb, nvg, nvb,
                                   lnq, lnk, lnv);

    dim3 gC(CDIM / 128, TOKENS / 128);
    gemm_tf32_kernel<3><<<gC, 256>>>(lnq, wq, bq, nullptr, qT, TOKENS, CDIM, CDIM);
    gemm_tf32_kernel<3><<<gC, 256>>>(lnk, wk, bk, nullptr, kT, TOKENS, CDIM, CDIM);
    gemm_tf32_kernel<0><<<gC, 256>>>(lnv, wv, bv, nullptr, v,  TOKENS, CDIM, CDIM);

    dim3 gA(NSEQ / 128, 4 * NHEADS);
    attn2_kernel<<<gA, 256, ATT_SMEM_BYTES>>>(qT, kT, v, ao);

    gemm_tf32_kernel<2><<<gC, 256>>>(ao, wp, bp, x, hbuf, TOKENS, CDIM, CDIM);

    ln_kernel<<<TOKENS, 256>>>(hbuf, ng, nb, lnh);

    dim3 gH(MLPH / 128, TOKENS / 128);
    gemm_tf32_kernel<1><<<gH, 256>>>(lnh, w1, b1, nullptr, m1, TOKENS, MLPH, CDIM);

    gemm_tf32_kernel<2><<<gC, 256>>>(m1, w2, b2, hbuf, out, TOKENS, CDIM, MLPH);
}

// round 9
// speedup vs baseline: 16.4460x; 1.4076x over previous
#include <cuda_runtime.h>
#include <math.h>

#define TOKENS 8192
#define NSEQ   2048
#define CDIM   1024
#define MLPH   4096
#define NHEADS 16
#define DHEAD  64
#define LN_EPS 1e-5f

#define SLAB 8388608ull
__device__ float g_scratch[9ull * SLAB + (unsigned long long)TOKENS * MLPH];

__device__ __forceinline__ float4 blockReduce4(float4 v) {
    __shared__ float4 red[8];
    #pragma unroll
    for (int o = 16; o > 0; o >>= 1) {
        v.x += __shfl_xor_sync(0xffffffffu, v.x, o);
        v.y += __shfl_xor_sync(0xffffffffu, v.y, o);
        v.z += __shfl_xor_sync(0xffffffffu, v.z, o);
        v.w += __shfl_xor_sync(0xffffffffu, v.w, o);
    }
    int w = threadIdx.x >> 5;
    if ((threadIdx.x & 31) == 0) red[w] = v;
    __syncthreads();
    v = red[threadIdx.x & 7];
    #pragma unroll
    for (int o = 4; o > 0; o >>= 1) {
        v.x += __shfl_xor_sync(0xffffffffu, v.x, o);
        v.y += __shfl_xor_sync(0xffffffffu, v.y, o);
        v.z += __shfl_xor_sync(0xffffffffu, v.z, o);
        v.w += __shfl_xor_sync(0xffffffffu, v.w, o);
    }
    return v;
}

__global__ __launch_bounds__(256) void ln_qkv_kernel(
    const float* __restrict__ x, const float* __restrict__ pe,
    const float* __restrict__ nqg, const float* __restrict__ nqb,
    const float* __restrict__ nkg, const float* __restrict__ nkb,
    const float* __restrict__ nvg, const float* __restrict__ nvb,
    float* __restrict__ lnq, float* __restrict__ lnk, float* __restrict__ lnv)
{
    int t = blockIdx.x;
    int n = t & (NSEQ - 1);
    int tid = threadIdx.x;

    const float4* xr = (const float4*)(x + (size_t)t * CDIM);
    const float4* pr = (const float4*)(pe + (size_t)n * CDIM);
    float4 xv = xr[tid];
    float4 pv = pr[tid];
    float4 xp = make_float4(xv.x + pv.x, xv.y + pv.y, xv.z + pv.z, xv.w + pv.w);

    float4 s;
    s.x = xv.x + xv.y + xv.z + xv.w;
    s.y = xv.x * xv.x + xv.y * xv.y + xv.z * xv.z + xv.w * xv.w;
    s.z = xp.x + xp.y + xp.z + xp.w;
    s.w = xp.x * xp.x + xp.y * xp.y + xp.z * xp.z + xp.w * xp.w;
    s = blockReduce4(s);

    const float inv = 1.0f / (float)CDIM;
    float m1 = s.x * inv, v1 = s.y * inv - m1 * m1;
    float r1 = rsqrtf(v1 + LN_EPS);
    float m2 = s.z * inv, v2 = s.w * inv - m2 * m2;
    float r2 = rsqrtf(v2 + LN_EPS);

    float4 g, b, o;
    size_t base = (size_t)t * CDIM;

    g = ((const float4*)nqg)[tid]; b = ((const float4*)nqb)[tid];
    o.x = (xv.x - m1) * r1 * g.x + b.x;
    o.y = (xv.y - m1) * r1 * g.y + b.y;
    o.z = (xv.z - m1) * r1 * g.z + b.z;
    o.w = (xv.w - m1) * r1 * g.w + b.w;
    ((float4*)(lnq + base))[tid] = o;

    float4 nrm;
    nrm.x = (xp.x - m2) * r2; nrm.y = (xp.y - m2) * r2;
    nrm.z = (xp.z - m2) * r2; nrm.w = (xp.w - m2) * r2;

    g = ((const float4*)nkg)[tid]; b = ((const float4*)nkb)[tid];
    o.x = nrm.x * g.x + b.x; o.y = nrm.y * g.y + b.y;
    o.z = nrm.z * g.z + b.z; o.w = nrm.w * g.w + b.w;
    ((float4*)(lnk + base))[tid] = o;

    g = ((const float4*)nvg)[tid]; b = ((const float4*)nvb)[tid];
    o.x = nrm.x * g.x + b.x; o.y = nrm.y * g.y + b.y;
    o.z = nrm.z * g.z + b.z; o.w = nrm.w * g.w + b.w;
    ((float4*)(lnv + base))[tid] = o;
}

__global__ __launch_bounds__(256) void ln_kernel(
    const float* __restrict__ in, const float* __restrict__ gg,
    const float* __restrict__ bb, float* __restrict__ out)
{
    int t = blockIdx.x;
    int tid = threadIdx.x;
    const float4* xr = (const float4*)(in + (size_t)t * CDIM);
    float4 xv = xr[tid];
    float4 s;
    s.x = xv.x + xv.y + xv.z + xv.w;
    s.y = xv.x * xv.x + xv.y * xv.y + xv.z * xv.z + xv.w * xv.w;
    s.z = 0.f; s.w = 0.f;
    s = blockReduce4(s);
    const float inv = 1.0f / (float)CDIM;
    float m = s.x * inv, v = s.y * inv - m * m;
    float r = rsqrtf(v + LN_EPS);
    float4 g = ((const float4*)gg)[tid];
    float4 b = ((const float4*)bb)[tid];
    float4 o;
    o.x = (xv.x - m) * r * g.x + b.x;
    o.y = (xv.y - m) * r * g.y + b.y;
    o.z = (xv.z - m) * r * g.z + b.z;
    o.w = (xv.w - m) * r * g.w + b.w;
    ((float4*)(out + (size_t)t * CDIM))[tid] = o;
}

// ---------------------------------------------------------------------------
// tf32 tensor-core helpers
// ---------------------------------------------------------------------------
__device__ __forceinline__ unsigned f2tf(float f) {
    unsigned u;
    asm("cvt.rna.tf32.f32 %0, %1;" : "=r"(u) : "f"(f));
    return u;
}

__device__ __forceinline__ void mma_tf32(float* d, const unsigned* a,
                                         const unsigned* b) {
    asm volatile(
        "mma.sync.aligned.m16n8k8.row.col.f32.tf32.tf32.f32 "
        "{%0,%1,%2,%3}, {%4,%5,%6,%7}, {%8,%9}, {%0,%1,%2,%3};\n"
        : "+f"(d[0]), "+f"(d[1]), "+f"(d[2]), "+f"(d[3])
        : "r"(a[0]), "r"(a[1]), "r"(a[2]), "r"(a[3]),
          "r"(b[0]), "r"(b[1]));
}

// ---------------------------------------------------------------------------
// tf32 GEMM, double-buffered smem, 128x128x16 tile, 8 warps (2x4), 64x32/warp.
// EPI: 0 bias ; 1 bias+LeakyReLU ; 2 bias+residual ; 3 bias+transposed store.
// ---------------------------------------------------------------------------
#define ASTR 20
#define BSTR 136

template <int EPI>
__global__ __launch_bounds__(256) void gemm_tf32_kernel(
    const float* __restrict__ X, const float* __restrict__ W,
    const float* __restrict__ bias, const float* __restrict__ Res,
    float* __restrict__ Y, int M, int N, int K)
{
    __shared__ unsigned As[2][128][ASTR];
    __shared__ unsigned Bs[2][16][BSTR];

    int tid = threadIdx.x;
    int bm = blockIdx.y * 128;
    int bn = blockIdx.x * 128;

    int warp = tid >> 5, lane = tid & 31;
    int wm = (warp & 1) * 64;
    int wn = (warp >> 1) * 32;
    int tg = lane & 3, gid = lane >> 2;

    int lr = tid >> 1;
    int lc = (tid & 1) * 8;
    int kr = warp;
    int nc = lane * 4;

    float acc[4][4][4];
    #pragma unroll
    for (int i = 0; i < 4; i++)
        #pragma unroll
        for (int j = 0; j < 4; j++)
            #pragma unroll
            for (int r = 0; r < 4; r++) acc[i][j][r] = 0.f;

    const float* Aptr = X + (size_t)(bm + lr) * K + lc;
    const float* Bptr = W + (size_t)kr * N + bn + nc;

    float4 a0v = *(const float4*)(Aptr);
    float4 a1v = *(const float4*)(Aptr + 4);
    float4 b0v = *(const float4*)(Bptr);
    float4 b1v = *(const float4*)(Bptr + (size_t)8 * N);

    *(uint4*)&As[0][lr][lc] =
        make_uint4(f2tf(a0v.x), f2tf(a0v.y), f2tf(a0v.z), f2tf(a0v.w));
    *(uint4*)&As[0][lr][lc + 4] =
        make_uint4(f2tf(a1v.x), f2tf(a1v.y), f2tf(a1v.z), f2tf(a1v.w));
    *(uint4*)&Bs[0][kr][nc] =
        make_uint4(f2tf(b0v.x), f2tf(b0v.y), f2tf(b0v.z), f2tf(b0v.w));
    *(uint4*)&Bs[0][kr + 8][nc] =
        make_uint4(f2tf(b1v.x), f2tf(b1v.y), f2tf(b1v.z), f2tf(b1v.w));
    __syncthreads();

    for (int k0 = 0; k0 < K; k0 += 16) {
        int cur = (k0 >> 4) & 1;
        int nxt = cur ^ 1;
        bool has_next = (k0 + 16 < K);

        if (has_next) {
            a0v = *(const float4*)(Aptr + k0 + 16);
            a1v = *(const float4*)(Aptr + k0 + 20);
            b0v = *(const float4*)(Bptr + (size_t)(k0 + 16) * N);
            b1v = *(const float4*)(Bptr + (size_t)(k0 + 24) * N);
        }

        #pragma unroll
        for (int kk = 0; kk < 16; kk += 8) {
            unsigned af[4][4];
            #pragma unroll
            for (int mi = 0; mi < 4; mi++) {
                int r = wm + mi * 16 + gid;
                af[mi][0] = As[cur][r][kk + tg];
                af[mi][1] = As[cur][r + 8][kk + tg];
                af[mi][2] = As[cur][r][kk + tg + 4];
                af[mi][3] = As[cur][r + 8][kk + tg + 4];
            }
            unsigned bf[4][2];
            #pragma unroll
            for (int ni = 0; ni < 4; ni++) {
                int c = wn + ni * 8 + gid;
                bf[ni][0] = Bs[cur][kk + tg][c];
                bf[ni][1] = Bs[cur][kk + tg + 4][c];
            }
            #pragma unroll
            for (int mi = 0; mi < 4; mi++)
                #pragma unroll
                for (int ni = 0; ni < 4; ni++)
                    mma_tf32(acc[mi][ni], af[mi], bf[ni]);
        }

        if (has_next) {
            *(uint4*)&As[nxt][lr][lc] =
                make_uint4(f2tf(a0v.x), f2tf(a0v.y), f2tf(a0v.z), f2tf(a0v.w));
            *(uint4*)&As[nxt][lr][lc + 4] =
                make_uint4(f2tf(a1v.x), f2tf(a1v.y), f2tf(a1v.z), f2tf(a1v.w));
            *(uint4*)&Bs[nxt][kr][nc] =
                make_uint4(f2tf(b0v.x), f2tf(b0v.y), f2tf(b0v.z), f2tf(b0v.w));
            *(uint4*)&Bs[nxt][kr + 8][nc] =
                make_uint4(f2tf(b1v.x), f2tf(b1v.y), f2tf(b1v.z), f2tf(b1v.w));
        }
        __syncthreads();
    }

    if (EPI == 3) {
        #pragma unroll
        for (int mi = 0; mi < 4; mi++) {
            int r0 = bm + wm + mi * 16 + gid;
            int r1 = r0 + 8;
            #pragma unroll
            for (int ni = 0; ni < 4; ni++) {
                int col = bn + wn + ni * 8 + 2 * tg;
                float bs0 = bias[col], bs1 = bias[col + 1];
                Y[(size_t)col * M + r0]       = acc[mi][ni][0] + bs0;
                Y[(size_t)(col + 1) * M + r0] = acc[mi][ni][1] + bs1;
                Y[(size_t)col * M + r1]       = acc[mi][ni][2] + bs0;
                Y[(size_t)(col + 1) * M + r1] = acc[mi][ni][3] + bs1;
            }
        }
        return;
    }

    #pragma unroll
    for (int mi = 0; mi < 4; mi++) {
        int r0 = bm + wm + mi * 16 + gid;
        int r1 = r0 + 8;
        #pragma unroll
        for (int ni = 0; ni < 4; ni++) {
            int col = bn + wn + ni * 8 + 2 * tg;
            float2 bs = *(const float2*)(bias + col);
            float2 v0, v1;
            v0.x = acc[mi][ni][0] + bs.x;
            v0.y = acc[mi][ni][1] + bs.y;
            v1.x = acc[mi][ni][2] + bs.x;
            v1.y = acc[mi][ni][3] + bs.y;
            if (EPI == 1) {
                v0.x = v0.x >= 0.f ? v0.x : 0.1f * v0.x;
                v0.y = v0.y >= 0.f ? v0.y : 0.1f * v0.y;
                v1.x = v1.x >= 0.f ? v1.x : 0.1f * v1.x;
                v1.y = v1.y >= 0.f ? v1.y : 0.1f * v1.y;
            }
            if (EPI == 2) {
                float2 q0 = *(const float2*)(Res + (size_t)r0 * N + col);
                float2 q1 = *(const float2*)(Res + (size_t)r1 * N + col);
                v0.x += q0.x; v0.y += q0.y;
                v1.x += q1.x; v1.y += q1.y;
            }
            *(float2*)(Y + (size_t)r0 * N + col) = v0;
            *(float2*)(Y + (size_t)r1 * N + col) = v1;
        }
    }
}

// ---------------------------------------------------------------------------
// Flash-attention v3: tf32 tensor cores for S and PV.
// Block = 128 q-tile x one (b,h). 8 warps; warp w owns q rows [16w,16w+16),
// full k=128 per warp -> softmax stays warp-local (thread owns rows gid,gid+8).
// smem (tf32 words): Qs[64][136], Ks[64][136], Vs[128][72], Ps[128][136].
// All frag-load patterns bank-perfect (addr ≡ 8*tg+gid mod 32).
// ---------------------------------------------------------------------------
#define AQ_STR 136
#define AV_STR 72
#define AP_STR 136
#define ATT3_QW  (64 * AQ_STR)
#define ATT3_VW  (128 * AV_STR)
#define ATT3_PW  (128 * AP_STR)
#define ATT3_SMEM_BYTES ((ATT3_QW * 2 + ATT3_VW + ATT3_PW) * 4)

__global__ __launch_bounds__(256) void attn3_kernel(
    const float* __restrict__ QT, const float* __restrict__ KT,
    const float* __restrict__ V, float* __restrict__ O)
{
    extern __shared__ unsigned usm[];
    unsigned* Qs = usm;
    unsigned* Ks = usm + ATT3_QW;
    unsigned* Vs = usm + 2 * ATT3_QW;
    unsigned* Ps = usm + 2 * ATT3_QW + ATT3_VW;

    int qt = blockIdx.x;
    int bh = blockIdx.y;
    int b = bh >> 4, h = bh & 15;

    int tid = threadIdx.x;
    int warp = tid >> 5, lane = tid & 31;
    int gid = lane >> 2, tg = lane & 3;
    int wq = warp * 16;

    const size_t tokbase = (size_t)b * NSEQ;
    const float* qtb = QT + (size_t)(h * DHEAD) * TOKENS + tokbase + (size_t)qt * 128;
    const float* ktb = KT + (size_t)(h * DHEAD) * TOKENS + tokbase;
    const float* vbg = V + tokbase * CDIM + h * DHEAD;

    const float scale = 0.125f;

    for (int i = tid; i < 64 * 32; i += 256) {
        int d = i >> 5, c = i & 31;
        float4 qv = ((const float4*)(qtb + (size_t)d * TOKENS))[c];
        *(uint4*)&Qs[d * AQ_STR + c * 4] =
            make_uint4(f2tf(qv.x * scale), f2tf(qv.y * scale),
                       f2tf(qv.z * scale), f2tf(qv.w * scale));
    }

    float m0 = -INFINITY, m1 = -INFINITY, l0 = 0.f, l1 = 0.f;
    float o[8][4];
    #pragma unroll
    for (int ni = 0; ni < 8; ni++)
        #pragma unroll
        for (int r = 0; r < 4; r++) o[ni][r] = 0.f;

    for (int kt = 0; kt < NSEQ / 128; kt++) {
        __syncthreads();
        for (int i = tid; i < 64 * 32; i += 256) {
            int d = i >> 5, c = i & 31;
            float4 kv = ((const float4*)(ktb + (size_t)d * TOKENS
                                         + (size_t)kt * 128))[c];
            *(uint4*)&Ks[d * AQ_STR + c * 4] =
                make_uint4(f2tf(kv.x), f2tf(kv.y), f2tf(kv.z), f2tf(kv.w));
        }
        for (int i = tid; i < 128 * 16; i += 256) {
            int k = i >> 4, c = i & 15;
            float4 vv = ((const float4*)(vbg + (size_t)(kt * 128 + k) * CDIM))[c];
            *(uint4*)&Vs[k * AV_STR + c * 4] =
                make_uint4(f2tf(vv.x), f2tf(vv.y), f2tf(vv.z), f2tf(vv.w));
        }
        __syncthreads();

        float s[16][4];
        #pragma unroll
        for (int ni = 0; ni < 16; ni++)
            #pragma unroll
            for (int r = 0; r < 4; r++) s[ni][r] = 0.f;

        #pragma unroll
        for (int d0 = 0; d0 < 64; d0 += 8) {
            unsigned af[4];
            af[0] = Qs[(d0 + tg) * AQ_STR + wq + gid];
            af[1] = Qs[(d0 + tg) * AQ_STR + wq + gid + 8];
            af[2] = Qs[(d0 + tg + 4) * AQ_STR + wq + gid];
            af[3] = Qs[(d0 + tg + 4) * AQ_STR + wq + gid + 8];
            #pragma unroll
            for (int ni = 0; ni < 16; ni++) {
                unsigned bf[2];
                bf[0] = Ks[(d0 + tg) * AQ_STR + ni * 8 + gid];
                bf[1] = Ks[(d0 + tg + 4) * AQ_STR + ni * 8 + gid];
                mma_tf32(s[ni], af, bf);
            }
        }

        float rm0 = -INFINITY, rm1 = -INFINITY;
        #pragma unroll
        for (int ni = 0; ni < 16; ni++) {
            rm0 = fmaxf(rm0, fmaxf(s[ni][0], s[ni][1]));
            rm1 = fmaxf(rm1, fmaxf(s[ni][2], s[ni][3]));
        }
        rm0 = fmaxf(rm0, __shfl_xor_sync(0xffffffffu, rm0, 1));
        rm0 = fmaxf(rm0, __shfl_xor_sync(0xffffffffu, rm0, 2));
        rm1 = fmaxf(rm1, __shfl_xor_sync(0xffffffffu, rm1, 1));
        rm1 = fmaxf(rm1, __shfl_xor_sync(0xffffffffu, rm1, 2));

        float mn0 = fmaxf(m0, rm0);
        float mn1 = fmaxf(m1, rm1);
        float al0 = __expf(m0 - mn0);
        float al1 = __expf(m1 - mn1);
        m0 = mn0; m1 = mn1;

        float rs0 = 0.f, rs1 = 0.f;
        #pragma unroll
        for (int ni = 0; ni < 16; ni++) {
            s[ni][0] = __expf(s[ni][0] - m0);
            s[ni][1] = __expf(s[ni][1] - m0);
            s[ni][2] = __expf(s[ni][2] - m1);
            s[ni][3] = __expf(s[ni][3] - m1);
            rs0 += s[ni][0] + s[ni][1];
            rs1 += s[ni][2] + s[ni][3];
        }
        rs0 += __shfl_xor_sync(0xffffffffu, rs0, 1);
        rs0 += __shfl_xor_sync(0xffffffffu, rs0, 2);
        rs1 += __shfl_xor_sync(0xffffffffu, rs1, 1);
        rs1 += __shfl_xor_sync(0xffffffffu, rs1, 2);
        l0 = l0 * al0 + rs0;
        l1 = l1 * al1 + rs1;

        #pragma unroll
        for (int ni = 0; ni < 8; ni++) {
            o[ni][0] *= al0; o[ni][1] *= al0;
            o[ni][2] *= al1; o[ni][3] *= al1;
        }

        #pragma unroll
        for (int ni = 0; ni < 16; ni++) {
            *(uint2*)&Ps[(wq + gid) * AP_STR + ni * 8 + 2 * tg] =
                make_uint2(f2tf(s[ni][0]), f2tf(s[ni][1]));
            *(uint2*)&Ps[(wq + gid + 8) * AP_STR + ni * 8 + 2 * tg] =
                make_uint2(f2tf(s[ni][2]), f2tf(s[ni][3]));
        }
        __syncwarp();

        #pragma unroll 4
        for (int k0 = 0; k0 < 128; k0 += 8) {
            unsigned af[4];
            af[0] = Ps[(wq + gid) * AP_STR + k0 + tg];
            af[1] = Ps[(wq + gid + 8) * AP_STR + k0 + tg];
            af[2] = Ps[(wq + gid) * AP_STR + k0 + tg + 4];
            af[3] = Ps[(wq + gid + 8) * AP_STR + k0 + tg + 4];
            #pragma unroll
            for (int ni = 0; ni < 8; ni++) {
                unsigned bf[2];
                bf[0] = Vs[(k0 + tg) * AV_STR + ni * 8 + gid];
                bf[1] = Vs[(k0 + tg + 4) * AV_STR + ni * 8 + gid];
                mma_tf32(o[ni], af, bf);
            }
        }
    }

    float inv0 = 1.0f / l0;
    float inv1 = 1.0f / l1;
    size_t row0 = tokbase + (size_t)qt * 128 + wq + gid;
    size_t row1 = row0 + 8;
    #pragma unroll
    for (int ni = 0; ni < 8; ni++) {
        int col = h * DHEAD + ni * 8 + 2 * tg;
        *(float2*)(O + row0 * CDIM + col) =
            make_float2(o[ni][0] * inv0, o[ni][1] * inv0);
        *(float2*)(O + row1 * CDIM + col) =
            make_float2(o[ni][2] * inv1, o[ni][3] * inv1);
    }
}

extern "C" void kernel_launch(void* const* d_in, const int* in_sizes, int n_in,
                              void* d_out, int out_size)
{
    bool dict_order = (in_sizes[8] == CDIM);

    const float* x   = (const float*)d_in[0];
    const float* pe  = (const float*)d_in[1];
    const float* nqg = (const float*)d_in[2];
    const float* nqb = (const float*)d_in[3];
    const float* nkg = (const float*)d_in[4];
    const float* nkb = (const float*)d_in[5];
    const float* nvg = (const float*)d_in[6];
    const float* nvb = (const float*)d_in[7];

    const float *ng, *nb, *wq, *bq, *wk, *bk, *wv, *bv, *wp, *bp,
                *w1, *b1, *w2, *b2;
    if (dict_order) {
        ng = (const float*)d_in[8];  nb = (const float*)d_in[9];
        wq = (const float*)d_in[10]; bq = (const float*)d_in[11];
        wk = (const float*)d_in[12]; bk = (const float*)d_in[13];
        wv = (const float*)d_in[14]; bv = (const float*)d_in[15];
        wp = (const float*)d_in[16]; bp = (const float*)d_in[17];
        w1 = (const float*)d_in[18]; b1 = (const float*)d_in[19];
        w2 = (const float*)d_in[20]; b2 = (const float*)d_in[21];
    } else {
        wq = (const float*)d_in[8];  bq = (const float*)d_in[9];
        wk = (const float*)d_in[10]; bk = (const float*)d_in[11];
        wv = (const float*)d_in[12]; bv = (const float*)d_in[13];
        wp = (const float*)d_in[14]; bp = (const float*)d_in[15];
        ng = (const float*)d_in[16]; nb = (const float*)d_in[17];
        w1 = (const float*)d_in[18]; b1 = (const float*)d_in[19];
        w2 = (const float*)d_in[20]; b2 = (const float*)d_in[21];
    }
    float* out = (float*)d_out;

    float* sc = nullptr;
    cudaGetSymbolAddress((void**)&sc, g_scratch);
    float* lnq = sc + 0 * SLAB;
    float* lnk = sc + 1 * SLAB;
    float* lnv = sc + 2 * SLAB;
    float* qT  = sc + 3 * SLAB;   // [CDIM][TOKENS]
    float* kT  = sc + 4 * SLAB;   // [CDIM][TOKENS]
    float* v   = sc + 5 * SLAB;   // [TOKENS][CDIM]
    float* ao  = sc + 6 * SLAB;
    float* hbuf= sc + 7 * SLAB;
    float* lnh = sc + 8 * SLAB;
    float* m1  = sc + 9 * SLAB;

    cudaFuncSetAttribute(attn3_kernel,
                         cudaFuncAttributeMaxDynamicSharedMemorySize,
                         ATT3_SMEM_BYTES);

    ln_qkv_kernel<<<TOKENS, 256>>>(x, pe, nqg, nqb, nkg, nkb, nvg, nvb,
                                   lnq, lnk, lnv);

    dim3 gC(CDIM / 128, TOKENS / 128);
    gemm_tf32_kernel<3><<<gC, 256>>>(lnq, wq, bq, nullptr, qT, TOKENS, CDIM, CDIM);
    gemm_tf32_kernel<3><<<gC, 256>>>(lnk, wk, bk, nullptr, kT, TOKENS, CDIM, CDIM);
    gemm_tf32_kernel<0><<<gC, 256>>>(lnv, wv, bv, nullptr, v,  TOKENS, CDIM, CDIM);

    dim3 gA(NSEQ / 128, 4 * NHEADS);
    attn3_kernel<<<gA, 256, ATT3_SMEM_BYTES>>>(qT, kT, v, ao);

    gemm_tf32_kernel<2><<<gC, 256>>>(ao, wp, bp, x, hbuf, TOKENS, CDIM, CDIM);

    ln_kernel<<<TOKENS, 256>>>(hbuf, ng, nb, lnh);

    dim3 gH(MLPH / 128, TOKENS / 128);
    gemm_tf32_kernel<1><<<gH, 256>>>(lnh, w1, b1, nullptr, m1, TOKENS, MLPH, CDIM);

    gemm_tf32_kernel<2><<<gC, 256>>>(m1, w2, b2, hbuf, out, TOKENS, CDIM, MLPH);
}